// round 13
// baseline (speedup 1.0000x reference)
#include <cuda_runtime.h>

// DRP_LAYER: 2D DRP-FDTD, 3 steps, B=2, N=2048.
// R13: 4-row coarsening with role-based row-phased accumulation.
// Each input row loaded once (merged span, f2 on padded buffers) and
// scattered into 4 per-thread output accumulators with static indices.

#define NN   2048
#define BB   2
#define CFLc 0.35f

#define ES   (NN + 1)
#define HXS  (NN)
#define HYS  (NN - 1)
#define ESZ  ((NN + 1) * (NN + 1))
#define HXSZ ((NN - 1) * NN)
#define HYSZ (NN * (NN - 1))

#define PE   2052
#define PHY  2048

__device__ __align__(16) float g_EpadA[BB * (NN + 1) * PE];
__device__ __align__(16) float g_EpadB[BB * (NN + 1) * PE];
__device__ __align__(16) float g_HyA[BB * NN * PHY];
__device__ __align__(16) float g_HyB[BB * NN * PHY];

__device__ float g_coef[2];

__global__ void coef_kernel(const float* __restrict__ beta,
                            const float* __restrict__ delta,
                            const float* __restrict__ gamma) {
    g_coef[0] = 0.25f * beta[0] - 0.1f * gamma[0];
    g_coef[1] = delta[0];
}

#define KF0 (-11.0f/6.0f)
#define KF1 (3.0f)
#define KF2 (-1.5f)
#define KF3 (1.0f/3.0f)
#define KB0 (-1.0f/3.0f)
#define KB1 (1.5f)
#define KB2 (-3.0f)
#define KB3 (11.0f/6.0f)

// Load up to 6 f2 (nf2 compile-time after unroll). VEC=aligned float2.
template<bool VEC>
__device__ __forceinline__ void load_span(float* dst, const float* p, int nf2) {
#pragma unroll
    for (int k = 0; k < 6; k++) {
        if (k < nf2) {
            if constexpr (VEC) {
                float2 v = reinterpret_cast<const float2*>(p)[k];
                dst[2*k] = v.x; dst[2*k+1] = v.y;
            } else {
                dst[2*k] = p[2*k]; dst[2*k+1] = p[2*k+1];
            }
        }
    }
}

// ---------------------------------------------------------------------------
// Ampere: E_out = E + CFL*(s1 - s2).
// Block (64,4): thread = col pair j0, rows r..r+3 (r = R0 + ty*4).
// ---------------------------------------------------------------------------
template<bool RAW>
__global__ __launch_bounds__(256, 5) void amper_kernel(
    const float* __restrict__ epad_in, const float* __restrict__ Hx,
    const float* __restrict__ hyp_in,
    float* __restrict__ eo_d, float* __restrict__ epad_out)
{
    constexpr int EI  = RAW ? ES  : PE;
    constexpr int HYI = RAW ? HYS : PHY;
    constexpr size_t EIB  = RAW ? (size_t)ESZ  : (size_t)ES * PE;
    constexpr size_t HYIB = RAW ? (size_t)HYSZ : (size_t)NN * PHY;
    constexpr bool V = !RAW;

    const int jb = blockIdx.x * 128;
    const int R0 = blockIdx.y * 16;
    const int tx = threadIdx.x;
    const int r  = R0 + threadIdx.y * 4;
    const int j0 = jb + 2 * tx;
    const int b  = blockIdx.z;

    const float* __restrict__ ein = epad_in + (size_t)b * EIB;
    const float* __restrict__ hx  = Hx      + (size_t)b * HXSZ;
    const float* __restrict__ hyp = hyp_in  + (size_t)b * HYIB;
    float* __restrict__ eo  = eo_d     + (size_t)b * ESZ;
    float* __restrict__ epo = epad_out + (size_t)b * ES * PE;

    const float u  = g_coef[0];
    const float dl = g_coef[1];
    const float c01 = u + dl - 0.5f;
    const float c11 = -2.0f * dl;
    const float c21 = dl + 0.5f - u;
    const float cKF = c21 + KF0;
    const float cKB = u + KB3;

    const bool fast = (R0 >= 8) && (R0 + 15 <= NN - 5) &&
                      (jb >= 128) && (jb + 127 <= NN - 5);

    if (fast) {
        float acc[4][2];
#pragma unroll
        for (int o = 0; o < 4; o++) { acc[o][0] = 0.0f; acc[o][1] = 0.0f; }

        // ---- Hy rows r-2..r+4, each loaded once, scattered to outputs ----
#pragma unroll
        for (int yy = -2; yy <= 4; yy++) {
            const bool hM2 = (yy >= -2 && yy <= 1);   // -> acc[yy+2]
            const bool hM1 = (yy >= -1 && yy <= 2);   // -> acc[yy+1]
            const bool hY0 = (yy >=  0 && yy <= 3);   // -> acc[yy]
            const bool hP1 = (yy >=  1 && yy <= 4);   // -> acc[yy-1]
            const int lo = hY0 ? -6 : -2;
            const int hi = hM1 ?  5 :  1;
            const int nf2 = (hi + 1 - lo) / 2;
            float buf[12];
            load_span<V>(buf, hyp + (r + yy) * HYI + (j0 + lo), nf2);
#pragma unroll
            for (int q = 0; q < 2; q++) {
#define X(d) buf[(q) + (d) - lo]
                if (hM2) acc[yy+2][q] += -u * X(-2) + u * X(0);
                if (hM1) acc[yy+1][q] += c01 * X(-2) + c11 * X(-1) + cKF * X(0)
                                       + KF1 * X(1) + KF2 * X(2) + KF3 * X(3);
                if (hY0) acc[yy][q]   += KB0 * X(-5) + KB1 * X(-4) + KB2 * X(-3)
                                       + cKB * X(-2) - u * X(0);
                if (hP1) acc[yy-1][q] += -u * X(-2) + u * X(0);
#undef X
            }
        }

        // ---- Hx rows r-5..r+6, each loaded once, scattered (subtracted) ----
#pragma unroll
        for (int xx = -5; xx <= 6; xx++) {
            const bool kb0 = (xx >= -5 && xx <= -2);  // -> acc[xx+5]
            const bool kb1 = (xx >= -4 && xx <= -1);  // -> acc[xx+4]
            const bool kb2 = (xx >= -3 && xx <=  0);  // -> acc[xx+3]
            const bool m2  = (xx >= -2 && xx <=  1);  // -> acc[xx+2]
            const bool cc  = (xx >= -1 && xx <=  2);  // -> acc[xx+1]
            const bool mn  = (xx >=  0 && xx <=  3);  // -> acc[xx]
            const bool kf1 = (xx >=  1 && xx <=  4);  // -> acc[xx-1]
            const bool kf2 = (xx >=  2 && xx <=  5);  // -> acc[xx-2]
            const bool kf3 = (xx >=  3 && xx <=  6);  // -> acc[xx-3]
            const int lo = (m2 || cc || mn || kf1 || kf2 || kf3) ? -2 : 0;
            const int hi = (m2 || mn) ? 3 : 1;
            const int nf2 = (hi + 1 - lo) / 2;
            float buf[6];
            load_span<true>(buf, hx + (r + xx) * HXS + (j0 + lo), nf2);
#pragma unroll
            for (int q = 0; q < 2; q++) {
#define X(d) buf[(q) + (d) - lo]
                if (kb0) acc[xx+5][q] -= KB0 * X(0);
                if (kb1) acc[xx+4][q] -= KB1 * X(0);
                if (kb2) acc[xx+3][q] -= KB2 * X(0);
                if (m2)  acc[xx+2][q] -= -u * X(-2) + c01 * X(-1) + cKB * X(0) - u * X(1);
                if (cc)  acc[xx+1][q] -= c11 * X(-1);
                if (mn)  acc[xx][q]   -=  u * X(-2) + cKF * X(-1) - u * X(0) + u * X(1);
                if (kf1) acc[xx-1][q] -= KF1 * X(-1);
                if (kf2) acc[xx-2][q] -= KF2 * X(-1);
                if (kf3) acc[xx-3][q] -= KF3 * X(-1);
#undef X
            }
        }

        // ---- epilogue ----
#pragma unroll
        for (int o = 0; o < 4; o++) {
            const int i = r + o;
            float ev[2];
            load_span<V>(ev, ein + (size_t)i * EI + j0, 1);
            const float o0 = ev[0] + CFLc * acc[o][0];
            const float o1 = ev[1] + CFLc * acc[o][1];
            eo[(size_t)i * ES + j0]     = o0;
            eo[(size_t)i * ES + j0 + 1] = o1;
            *reinterpret_cast<float2*>(epo + (size_t)i * PE + j0) = make_float2(o0, o1);
        }
        return;
    }

    // ---- generic path (edges) ----
#define HXg(rr,cc) hx[(rr) * HXS + (cc)]
#define HYg(rr,cc) hyp[(rr) * HYI + (cc)]
    for (int rr = 0; rr < 4; rr++) {
        const int i = r + rr;
        if (i > NN) break;
#pragma unroll
        for (int q = 0; q < 2; q++) {
            const int j = j0 + q;
            if (j > NN) break;

            const bool iin = (i >= 2) && (i <= NN - 2);
            const bool jin = (j >= 2) && (j <= NN - 2);

            float s1 = 0.0f;
            if (iin && jin) {
                s1 += -u  * HYg(i-2, j-2) + u   * HYg(i-2, j)
                    + c01 * HYg(i-1, j-2) + c11 * HYg(i-1, j-1) + c21 * HYg(i-1, j)
                    + u   * HYg(i  , j-2) - u   * HYg(i  , j)
                    - u   * HYg(i+1, j-2) + u   * HYg(i+1, j);
            }
            if (i >= 1 && j <= NN - 5)
                s1 += KF0*HYg(i-1, j) + KF1*HYg(i-1, j+1) + KF2*HYg(i-1, j+2) + KF3*HYg(i-1, j+3);
            if (i <= NN - 1 && j >= 5)
                s1 += KB0*HYg(i, j-5) + KB1*HYg(i, j-4) + KB2*HYg(i, j-3) + KB3*HYg(i, j-2);
            if (iin && (j == 1 || j == 2))
                s1 += -HYg(i-1, j-1) + 3.0f*HYg(i-1, j) - 3.0f*HYg(i-1, j+1) + HYg(i-1, j+2);
            if (iin && (j == NN-2 || j == NN-1))
                s1 += HYg(i, j-4) - 3.0f*HYg(i, j-3) + 3.0f*HYg(i, j-2) - HYg(i, j-1);

            float s2 = 0.0f;
            if (iin && jin) {
                s2 += -u  * HXg(i-2, j-2) + c01 * HXg(i-2, j-1) + u * HXg(i-2, j) - u * HXg(i-2, j+1)
                    + c11 * HXg(i-1, j-1)
                    + u   * HXg(i  , j-2) + c21 * HXg(i  , j-1) - u * HXg(i  , j) + u * HXg(i  , j+1);
            }
            if (i <= NN - 5 && j >= 1)
                s2 += KF0*HXg(i, j-1) + KF1*HXg(i+1, j-1) + KF2*HXg(i+2, j-1) + KF3*HXg(i+3, j-1);
            if (i >= 5 && j <= NN - 1)
                s2 += KB0*HXg(i-5, j) + KB1*HXg(i-4, j) + KB2*HXg(i-3, j) + KB3*HXg(i-2, j);
            if ((i == 1 || i == 2) && jin)
                s2 += -HXg(i-1, j-1) + 3.0f*HXg(i, j-1) - 3.0f*HXg(i+1, j-1) + HXg(i+2, j-1);
            if ((i == NN-2 || i == NN-1) && jin)
                s2 += HXg(i-4, j) - 3.0f*HXg(i-3, j) + 3.0f*HXg(i-2, j) - HXg(i-1, j);

            const float val = ein[(size_t)i * EI + j] + CFLc * (s1 - s2);
            eo[(size_t)i * ES + j] = val;
            epo[(size_t)i * PE + j] = val;
        }
    }
#undef HXg
#undef HYg
}

// ---------------------------------------------------------------------------
// Faraday: Hx_out = Hx - CFL*s3 ; Hy_out = Hy + CFL*s4
// Block (64,4): thread = col pair j0, rows i0..i0+3 (i0 = R0 + ty*4, even).
// ---------------------------------------------------------------------------
template<bool RAWHY>
__global__ __launch_bounds__(256, 5) void faraday_kernel(
    const float* __restrict__ epad_in, const float* __restrict__ Hx,
    const float* __restrict__ hyp_in,
    float* __restrict__ hxo_d, float* __restrict__ hyo_d,
    float* __restrict__ hyp_out)
{
    constexpr int HYI = RAWHY ? HYS : PHY;
    constexpr size_t HYIB = RAWHY ? (size_t)HYSZ : (size_t)NN * PHY;
    constexpr bool V = !RAWHY;

    const int jb = blockIdx.x * 128;
    const int R0 = blockIdx.y * 16;
    const int tx = threadIdx.x;
    const int i0 = R0 + threadIdx.y * 4;
    const int j0 = jb + 2 * tx;
    const int b  = blockIdx.z;

    const float* __restrict__ ein = epad_in + (size_t)b * ES * PE;
    const float* __restrict__ hx  = Hx      + (size_t)b * HXSZ;
    const float* __restrict__ hyp = hyp_in  + (size_t)b * HYIB;
    float* __restrict__ hxo = hxo_d   + (size_t)b * HXSZ;
    float* __restrict__ hyo = hyo_d   + (size_t)b * HYSZ;
    float* __restrict__ hpo = hyp_out + (size_t)b * NN * PHY;

    const float u  = g_coef[0];
    const float dl = g_coef[1];
    const float c01 = u + dl - 0.5f;
    const float c11 = -2.0f * dl;
    const float c21 = dl + 0.5f - u;

    const bool fast = (R0 >= 8) && (R0 + 15 <= NN - 4) &&
                      (jb >= 128) && (jb + 127 <= NN - 4);

    if (fast) {
        float s3a[4][2], s4a[4][2];
#pragma unroll
        for (int o = 0; o < 4; o++) { s3a[o][0]=0.f; s3a[o][1]=0.f; s4a[o][0]=0.f; s4a[o][1]=0.f; }

        // ---- E rows i0-1..i0+6, each loaded once, scattered ----
#pragma unroll
        for (int ee = -1; ee <= 6; ee++) {
            const bool em1 = (ee >= -1 && ee <= 2);   // -> o = ee+1
            const bool e0r = (ee >=  0 && ee <= 3);   // -> o = ee
            const bool ep1 = (ee >=  1 && ee <= 4);   // -> o = ee-1
            const bool ep2 = (ee >=  2 && ee <= 5);   // -> o = ee-2
            const bool ep3 = (ee >=  3 && ee <= 6);   // -> o = ee-3
            const int lo = (e0r || ep1 || ep2) ? -2 : 0;
            const int hi = e0r ? 5 : ((em1 || ep1 || ep2) ? 3 : 1);
            const int nf2 = (hi + 1 - lo) / 2;
            float buf[8];
            load_span<true>(buf, ein + (i0 + ee) * PE + (j0 + lo), nf2);
#pragma unroll
            for (int q = 0; q < 2; q++) {
#define X(d) buf[(q) + (d) - lo]
                if (em1) {
                    s3a[ee+1][q] += 0.5f * X(1);
                    s4a[ee+1][q] += -u * X(0) + u * X(2);
                }
                if (e0r) {
                    s3a[ee][q] += -u * X(-1) + c01 * X(0) + (u - 2.0f) * X(1) - u * X(2);
                    s4a[ee][q] += c01 * X(0) + (c11 - 1.5f) * X(1)
                                + (c21 + 2.0f) * X(2) - 0.5f * X(3);
                }
                if (ep1) {
                    s3a[ee-1][q] += (c11 - 1.5f) * X(0) + 1.5f * X(1);
                    s4a[ee-1][q] += 0.5f * X(-1) + (u - 2.0f) * X(0) + 1.5f * X(1) - u * X(2);
                }
                if (ep2) {
                    s3a[ee-2][q] += u * X(-1) + (c21 + 2.0f) * X(0) - u * X(1) + u * X(2);
                    s4a[ee-2][q] += -u * X(0) + u * X(2);
                }
                if (ep3) {
                    s3a[ee-3][q] += -0.5f * X(0);
                }
#undef X
            }
        }

        // ---- epilogue ----
#pragma unroll
        for (int o = 0; o < 4; o++) {
            const int i = i0 + o;
            float hyv[2];
            load_span<V>(hyv, hyp + (size_t)i * HYI + j0, 1);
            float2 hxp = *reinterpret_cast<const float2*>(hx + (size_t)i * HXS + j0);
            const float x0 = hxp.x - CFLc * s3a[o][0];
            const float x1 = hxp.y - CFLc * s3a[o][1];
            const float y0 = hyv[0] + CFLc * s4a[o][0];
            const float y1 = hyv[1] + CFLc * s4a[o][1];
            *reinterpret_cast<float2*>(hxo + (size_t)i * HXS + j0) = make_float2(x0, x1);
            if ((o & 1) == 0) {   // i even: hyo f2 store aligned
                *reinterpret_cast<float2*>(hyo + (size_t)i * HYS + j0) = make_float2(y0, y1);
            } else {
                hyo[(size_t)i * HYS + j0]     = y0;
                hyo[(size_t)i * HYS + j0 + 1] = y1;
            }
            *reinterpret_cast<float2*>(hpo + (size_t)i * PHY + j0) = make_float2(y0, y1);
        }
        return;
    }

    // ---- generic path (edges) ----
#define EEg(rr,cc) ein[(rr) * PE + (cc)]
    for (int rr = 0; rr < 4; rr++) {
        const int i = i0 + rr;
        if (i >= NN) break;
#pragma unroll
        for (int q = 0; q < 2; q++) {
            const int j = j0 + q;
            if (j >= NN) break;

            if (i <= NN - 2) {
                float s3 = 0.0f;
                if (j >= 1 && j <= NN - 2) {
                    s3 += -u  * EEg(i  , j-1) + c01 * EEg(i  , j) + u * EEg(i  , j+1) - u * EEg(i  , j+2)
                        + c11 * EEg(i+1, j)
                        + u   * EEg(i+2, j-1) + c21 * EEg(i+2, j) - u * EEg(i+2, j+1) + u * EEg(i+2, j+2);
                }
                if (i <= NN - 4)
                    s3 += -1.5f * EEg(i+1, j) + 2.0f * EEg(i+2, j) - 0.5f * EEg(i+3, j);
                if (i >= 2)
                    s3 +=  0.5f * EEg(i-1, j+1) - 2.0f * EEg(i, j+1) + 1.5f * EEg(i+1, j+1);
                hxo[(size_t)i * HXS + j] = hx[(size_t)i * HXS + j] - CFLc * s3;
            }

            if (j <= NN - 2) {
                float s4 = 0.0f;
                if (i >= 1 && i <= NN - 2) {
                    s4 += -u  * EEg(i-1, j) + u * EEg(i-1, j+2)
                        + c01 * EEg(i  , j) + c11 * EEg(i, j+1) + c21 * EEg(i, j+2)
                        + u   * EEg(i+1, j) - u * EEg(i+1, j+2)
                        - u   * EEg(i+2, j) + u * EEg(i+2, j+2);
                }
                if (j <= NN - 4)
                    s4 += -1.5f * EEg(i, j+1) + 2.0f * EEg(i, j+2) - 0.5f * EEg(i, j+3);
                if (j >= 2)
                    s4 +=  0.5f * EEg(i+1, j-1) - 2.0f * EEg(i+1, j) + 1.5f * EEg(i+1, j+1);
                const float val = hyp[(size_t)i * HYI + j] + CFLc * s4;
                hyo[(size_t)i * HYS + j] = val;
                hpo[(size_t)i * PHY + j] = val;
            }
        }
    }
#undef EEg
}

// ---------------------------------------------------------------------------
extern "C" void kernel_launch(void* const* d_in, const int* in_sizes, int n_in,
                              void* d_out, int out_size)
{
    const float* E0    = (const float*)d_in[0];
    const float* Hx0   = (const float*)d_in[1];
    const float* Hy0   = (const float*)d_in[2];
    const float* beta  = (const float*)d_in[3];
    const float* delta = (const float*)d_in[4];
    const float* gamma = (const float*)d_in[5];

    float* out = (float*)d_out;
    const size_t esz  = (size_t)BB * ESZ;
    const size_t hxsz = (size_t)BB * HXSZ;
    const size_t hysz = (size_t)BB * HYSZ;

    float* E2  = out;
    float* Hx2 = E2  + esz;
    float* Hy2 = Hx2 + hxsz;
    float* E3  = Hy2 + hysz;
    float* Hx3 = E3  + esz;
    float* Hy3 = Hx3 + hxsz;
    float* E4  = Hy3 + hysz;
    float* Hx4 = E4  + esz;
    float* Hy4 = Hx4 + hxsz;

    float *EA, *EB, *HA, *HB;
    cudaGetSymbolAddress((void**)&EA, g_EpadA);
    cudaGetSymbolAddress((void**)&EB, g_EpadB);
    cudaGetSymbolAddress((void**)&HA, g_HyA);
    cudaGetSymbolAddress((void**)&HB, g_HyB);

    coef_kernel<<<1, 1>>>(beta, delta, gamma);

    dim3 blk(64, 4, 1);
    dim3 gE(17, (ES + 15) / 16, BB);   // 17 x 129 x 2
    dim3 gF(16, NN / 16, BB);          // 16 x 128 x 2

    // step 1 — raw inputs
    amper_kernel<true>   <<<gE, blk>>>(E0, Hx0, Hy0, E2, EB);
    faraday_kernel<true> <<<gF, blk>>>(EB, Hx0, Hy0, Hx2, Hy2, HB);
    // step 2 — padded inputs
    amper_kernel<false>  <<<gE, blk>>>(EB, Hx2, HB, E3, EA);
    faraday_kernel<false><<<gF, blk>>>(EA, Hx2, HB, Hx3, Hy3, HA);
    // step 3
    amper_kernel<false>  <<<gE, blk>>>(EA, Hx3, HA, E4, EB);
    faraday_kernel<false><<<gF, blk>>>(EB, Hx3, HA, Hx4, Hy4, HB);
}

// round 14
// speedup vs baseline: 1.0397x; 1.0397x over previous
#include <cuda_runtime.h>

// DRP_LAYER: 2D DRP-FDTD, 3 steps, B=2, N=2048.
// R14: R12 (2-row merged buffers, raw-input step 1, no repack) with
// __launch_bounds__(256,6) — 42-reg cap, 6 blocks/SM occupancy push.

#define NN   2048
#define BB   2
#define CFLc 0.35f

#define ES   (NN + 1)
#define HXS  (NN)
#define HYS  (NN - 1)
#define ESZ  ((NN + 1) * (NN + 1))
#define HXSZ ((NN - 1) * NN)
#define HYSZ (NN * (NN - 1))

#define PE   2052
#define PHY  2048

__device__ __align__(16) float g_EpadA[BB * (NN + 1) * PE];
__device__ __align__(16) float g_EpadB[BB * (NN + 1) * PE];
__device__ __align__(16) float g_HyA[BB * NN * PHY];
__device__ __align__(16) float g_HyB[BB * NN * PHY];

__device__ float g_coef[2];

__global__ void coef_kernel(const float* __restrict__ beta,
                            const float* __restrict__ delta,
                            const float* __restrict__ gamma) {
    g_coef[0] = 0.25f * beta[0] - 0.1f * gamma[0];
    g_coef[1] = delta[0];
}

#define KF0 (-11.0f/6.0f)
#define KF1 (3.0f)
#define KF2 (-1.5f)
#define KF3 (1.0f/3.0f)
#define KB0 (-1.0f/3.0f)
#define KB1 (1.5f)
#define KB2 (-3.0f)
#define KB3 (11.0f/6.0f)

// Load NP float2-pairs (2*NP floats). VEC=true uses aligned float2 loads.
template<int NP, bool VEC>
__device__ __forceinline__ void ldrow(float* dst, const float* p) {
    if constexpr (VEC) {
        const float2* q = reinterpret_cast<const float2*>(p);
#pragma unroll
        for (int k = 0; k < NP; k++) { float2 v = q[k]; dst[2*k] = v.x; dst[2*k+1] = v.y; }
    } else {
#pragma unroll
        for (int k = 0; k < 2 * NP; k++) dst[k] = p[k];
    }
}

// ---------------------------------------------------------------------------
// Ampere: E_out = E + CFL*(s1 - s2).
// Block (64,4): thread = col pair j0 = jb+2tx, rows r = R0+2ty, r+1.
// RAW=true: E/Hy inputs are the raw odd-stride tensors (step 1).
// ---------------------------------------------------------------------------
template<bool RAW>
__global__ __launch_bounds__(256, 6) void amper_kernel(
    const float* __restrict__ epad_in, const float* __restrict__ Hx,
    const float* __restrict__ hyp_in,
    float* __restrict__ eo_d, float* __restrict__ epad_out)
{
    constexpr int EI  = RAW ? ES  : PE;    // E input stride
    constexpr int HYI = RAW ? HYS : PHY;   // Hy input stride
    constexpr size_t EIB  = RAW ? (size_t)ESZ  : (size_t)ES * PE;
    constexpr size_t HYIB = RAW ? (size_t)HYSZ : (size_t)NN * PHY;
    constexpr bool V = !RAW;

    const int jb = blockIdx.x * 128;
    const int R0 = blockIdx.y * 8;
    const int tx = threadIdx.x;
    const int r  = R0 + threadIdx.y * 2;
    const int j0 = jb + 2 * tx;
    const int b  = blockIdx.z;

    const float* __restrict__ ein = epad_in + (size_t)b * EIB;
    const float* __restrict__ hx  = Hx      + (size_t)b * HXSZ;
    const float* __restrict__ hyp = hyp_in  + (size_t)b * HYIB;
    float* __restrict__ eo  = eo_d     + (size_t)b * ESZ;
    float* __restrict__ epo = epad_out + (size_t)b * ES * PE;

    const float u  = g_coef[0];
    const float dl = g_coef[1];
    const float c01 = u + dl - 0.5f;
    const float c11 = -2.0f * dl;
    const float c21 = dl + 0.5f - u;
    const float cKF = c21 + KF0;
    const float cKB = u + KB3;

    const bool fast = (R0 >= 8) && (R0 + 7 <= NN - 5) &&
                      (jb >= 128) && (jb + 127 <= NN - 5);

    if (fast) {
        float acc[2][2];

        // ---- Hy rows r-2..r+2, merged spans ----
        {
            float hm2[4], hm1[8], h0[12], hp1[8], hp2[4];
            ldrow<2, V>(hm2, hyp + (r-2) * HYI + (j0-2));
            ldrow<4, V>(hm1, hyp + (r-1) * HYI + (j0-2));
            ldrow<6, V>(h0 , hyp + (r  ) * HYI + (j0-6));
            ldrow<4, V>(hp1, hyp + (r+1) * HYI + (j0-6));
            ldrow<2, V>(hp2, hyp + (r+2) * HYI + (j0-2));
#pragma unroll
            for (int q = 0; q < 2; q++) {
                acc[0][q] =
                      -u * hm2[q] + u * hm2[q+2]
                    + c01 * hm1[q] + c11 * hm1[q+1] + cKF * hm1[q+2]
                    + KF1 * hm1[q+3] + KF2 * hm1[q+4] + KF3 * hm1[q+5]
                    + KB0 * h0[q+1] + KB1 * h0[q+2] + KB2 * h0[q+3]
                    + cKB * h0[q+4] - u * h0[q+6]
                    - u * hp1[q+4] + u * hp1[q+6];
                acc[1][q] =
                      -u * hm1[q] + u * hm1[q+2]
                    + c01 * h0[q+4] + c11 * h0[q+5] + cKF * h0[q+6]
                    + KF1 * h0[q+7] + KF2 * h0[q+8] + KF3 * h0[q+9]
                    + KB0 * hp1[q+1] + KB1 * hp1[q+2] + KB2 * hp1[q+3]
                    + cKB * hp1[q+4] - u * hp1[q+6]
                    - u * hp2[q] + u * hp2[q+2];
            }
        }

        // ---- Hx rows r-5..r+4, merged spans (Hx always even-stride) ----
        {
            float a5[2], a4[2], a3[2], a2[6], a1[6], a0[6], b1[6], b2[4], b3[4], b4[4];
            ldrow<1, true>(a5, hx + (r-5) * HXS + j0);
            ldrow<1, true>(a4, hx + (r-4) * HXS + j0);
            ldrow<1, true>(a3, hx + (r-3) * HXS + j0);
            ldrow<3, true>(a2, hx + (r-2) * HXS + (j0-2));
            ldrow<3, true>(a1, hx + (r-1) * HXS + (j0-2));
            ldrow<3, true>(a0, hx + (r  ) * HXS + (j0-2));
            ldrow<3, true>(b1, hx + (r+1) * HXS + (j0-2));
            ldrow<2, true>(b2, hx + (r+2) * HXS + (j0-2));
            ldrow<2, true>(b3, hx + (r+3) * HXS + (j0-2));
            ldrow<2, true>(b4, hx + (r+4) * HXS + (j0-2));
#pragma unroll
            for (int q = 0; q < 2; q++) {
                acc[0][q] -=
                      KB0 * a5[q] + KB1 * a4[q] + KB2 * a3[q]
                    - u * a2[q] + c01 * a2[q+1] + cKB * a2[q+2] - u * a2[q+3]
                    + c11 * a1[q+1]
                    + u * a0[q] + cKF * a0[q+1] - u * a0[q+2] + u * a0[q+3]
                    + KF1 * b1[q+1] + KF2 * b2[q+1] + KF3 * b3[q+1];
                acc[1][q] -=
                      KB0 * a4[q] + KB1 * a3[q] + KB2 * a2[q+2]
                    - u * a1[q] + c01 * a1[q+1] + cKB * a1[q+2] - u * a1[q+3]
                    + c11 * a0[q+1]
                    + u * b1[q] + cKF * b1[q+1] - u * b1[q+2] + u * b1[q+3]
                    + KF1 * b2[q+1] + KF2 * b3[q+1] + KF3 * b4[q+1];
            }
        }

        // ---- epilogue ----
#pragma unroll
        for (int rr = 0; rr < 2; rr++) {
            const int i = r + rr;
            float tmp[2];
            ldrow<1, V>(tmp, ein + (size_t)i * EI + j0);
            const float o0 = tmp[0] + CFLc * acc[rr][0];
            const float o1 = tmp[1] + CFLc * acc[rr][1];
            eo[(size_t)i * ES + j0]     = o0;
            eo[(size_t)i * ES + j0 + 1] = o1;
            *reinterpret_cast<float2*>(epo + (size_t)i * PE + j0) = make_float2(o0, o1);
        }
        return;
    }

    // ---- generic path (edges) ----
#define HXg(rr,cc) hx[(rr) * HXS + (cc)]
#define HYg(rr,cc) hyp[(rr) * HYI + (cc)]
    for (int rr = 0; rr < 2; rr++) {
        const int i = r + rr;
        if (i > NN) break;
#pragma unroll
        for (int q = 0; q < 2; q++) {
            const int j = j0 + q;
            if (j > NN) break;

            const bool iin = (i >= 2) && (i <= NN - 2);
            const bool jin = (j >= 2) && (j <= NN - 2);

            float s1 = 0.0f;
            if (iin && jin) {
                s1 += -u  * HYg(i-2, j-2) + u   * HYg(i-2, j)
                    + c01 * HYg(i-1, j-2) + c11 * HYg(i-1, j-1) + c21 * HYg(i-1, j)
                    + u   * HYg(i  , j-2) - u   * HYg(i  , j)
                    - u   * HYg(i+1, j-2) + u   * HYg(i+1, j);
            }
            if (i >= 1 && j <= NN - 5)
                s1 += KF0*HYg(i-1, j) + KF1*HYg(i-1, j+1) + KF2*HYg(i-1, j+2) + KF3*HYg(i-1, j+3);
            if (i <= NN - 1 && j >= 5)
                s1 += KB0*HYg(i, j-5) + KB1*HYg(i, j-4) + KB2*HYg(i, j-3) + KB3*HYg(i, j-2);
            if (iin && (j == 1 || j == 2))
                s1 += -HYg(i-1, j-1) + 3.0f*HYg(i-1, j) - 3.0f*HYg(i-1, j+1) + HYg(i-1, j+2);
            if (iin && (j == NN-2 || j == NN-1))
                s1 += HYg(i, j-4) - 3.0f*HYg(i, j-3) + 3.0f*HYg(i, j-2) - HYg(i, j-1);

            float s2 = 0.0f;
            if (iin && jin) {
                s2 += -u  * HXg(i-2, j-2) + c01 * HXg(i-2, j-1) + u * HXg(i-2, j) - u * HXg(i-2, j+1)
                    + c11 * HXg(i-1, j-1)
                    + u   * HXg(i  , j-2) + c21 * HXg(i  , j-1) - u * HXg(i  , j) + u * HXg(i  , j+1);
            }
            if (i <= NN - 5 && j >= 1)
                s2 += KF0*HXg(i, j-1) + KF1*HXg(i+1, j-1) + KF2*HXg(i+2, j-1) + KF3*HXg(i+3, j-1);
            if (i >= 5 && j <= NN - 1)
                s2 += KB0*HXg(i-5, j) + KB1*HXg(i-4, j) + KB2*HXg(i-3, j) + KB3*HXg(i-2, j);
            if ((i == 1 || i == 2) && jin)
                s2 += -HXg(i-1, j-1) + 3.0f*HXg(i, j-1) - 3.0f*HXg(i+1, j-1) + HXg(i+2, j-1);
            if ((i == NN-2 || i == NN-1) && jin)
                s2 += HXg(i-4, j) - 3.0f*HXg(i-3, j) + 3.0f*HXg(i-2, j) - HXg(i-1, j);

            const float val = ein[(size_t)i * EI + j] + CFLc * (s1 - s2);
            eo[(size_t)i * ES + j] = val;
            epo[(size_t)i * PE + j] = val;
        }
    }
#undef HXg
#undef HYg
}

// ---------------------------------------------------------------------------
// Faraday: Hx_out = Hx - CFL*s3 ; Hy_out = Hy + CFL*s4
// Block (64,4): thread = col pair j0, rows i = R0+2ty (even), i+1.
// RAWHY=true: Hy input is the raw odd-stride tensor (step 1).
// ---------------------------------------------------------------------------
template<bool RAWHY>
__global__ __launch_bounds__(256, 6) void faraday_kernel(
    const float* __restrict__ epad_in, const float* __restrict__ Hx,
    const float* __restrict__ hyp_in,
    float* __restrict__ hxo_d, float* __restrict__ hyo_d,
    float* __restrict__ hyp_out)
{
    constexpr int HYI = RAWHY ? HYS : PHY;
    constexpr size_t HYIB = RAWHY ? (size_t)HYSZ : (size_t)NN * PHY;
    constexpr bool V = !RAWHY;

    const int jb = blockIdx.x * 128;
    const int R0 = blockIdx.y * 8;
    const int tx = threadIdx.x;
    const int i0 = R0 + threadIdx.y * 2;
    const int j0 = jb + 2 * tx;
    const int b  = blockIdx.z;

    const float* __restrict__ ein = epad_in + (size_t)b * ES * PE;
    const float* __restrict__ hx  = Hx      + (size_t)b * HXSZ;
    const float* __restrict__ hyp = hyp_in  + (size_t)b * HYIB;
    float* __restrict__ hxo = hxo_d   + (size_t)b * HXSZ;
    float* __restrict__ hyo = hyo_d   + (size_t)b * HYSZ;
    float* __restrict__ hpo = hyp_out + (size_t)b * NN * PHY;

    const float u  = g_coef[0];
    const float dl = g_coef[1];
    const float c01 = u + dl - 0.5f;
    const float c11 = -2.0f * dl;
    const float c21 = dl + 0.5f - u;

    const bool fast = (R0 >= 8) && (R0 + 7 <= NN - 4) &&
                      (jb >= 128) && (jb + 127 <= NN - 4);

    if (fast) {
        float fm1[4], f0[8], f1[8], f2[6], f3[6], f4[2];
        ldrow<2, true>(fm1, ein + (i0-1) * PE + j0);
        ldrow<4, true>(f0 , ein + (i0  ) * PE + (j0-2));
        ldrow<4, true>(f1 , ein + (i0+1) * PE + (j0-2));
        ldrow<3, true>(f2 , ein + (i0+2) * PE + (j0-2));
        ldrow<3, true>(f3 , ein + (i0+3) * PE + (j0-2));
        ldrow<1, true>(f4 , ein + (i0+4) * PE + j0);

        float s3v[2][2], s4v[2][2];
#pragma unroll
        for (int q = 0; q < 2; q++) {
            s3v[0][q] = 0.5f * fm1[q+1]
                      - u * f0[q+1] + c01 * f0[q+2] + (u - 2.0f) * f0[q+3] - u * f0[q+4]
                      + (c11 - 1.5f) * f1[q+2] + 1.5f * f1[q+3]
                      + u * f2[q+1] + (c21 + 2.0f) * f2[q+2] - u * f2[q+3] + u * f2[q+4]
                      - 0.5f * f3[q+2];
            s4v[0][q] = -u * fm1[q] + u * fm1[q+2]
                      + c01 * f0[q+2] + (c11 - 1.5f) * f0[q+3]
                      + (c21 + 2.0f) * f0[q+4] - 0.5f * f0[q+5]
                      + 0.5f * f1[q+1] + (u - 2.0f) * f1[q+2] + 1.5f * f1[q+3] - u * f1[q+4]
                      - u * f2[q+2] + u * f2[q+4];
            s3v[1][q] = 0.5f * f0[q+3]
                      - u * f1[q+1] + c01 * f1[q+2] + (u - 2.0f) * f1[q+3] - u * f1[q+4]
                      + (c11 - 1.5f) * f2[q+2] + 1.5f * f2[q+3]
                      + u * f3[q+1] + (c21 + 2.0f) * f3[q+2] - u * f3[q+3] + u * f3[q+4]
                      - 0.5f * f4[q];
            s4v[1][q] = -u * f0[q+2] + u * f0[q+4]
                      + c01 * f1[q+2] + (c11 - 1.5f) * f1[q+3]
                      + (c21 + 2.0f) * f1[q+4] - 0.5f * f1[q+5]
                      + 0.5f * f2[q+1] + (u - 2.0f) * f2[q+2] + 1.5f * f2[q+3] - u * f2[q+4]
                      - u * f3[q+2] + u * f3[q+4];
        }

        // row i0 (even): hyo d_out f2 store aligned (HYSZ, i0*HYS, j0 even)
        {
            float hyv[2];
            ldrow<1, V>(hyv, hyp + (size_t)i0 * HYI + j0);
            float2 hxp = *reinterpret_cast<const float2*>(hx + (size_t)i0 * HXS + j0);
            const float x0 = hxp.x - CFLc * s3v[0][0];
            const float x1 = hxp.y - CFLc * s3v[0][1];
            const float y0 = hyv[0] + CFLc * s4v[0][0];
            const float y1 = hyv[1] + CFLc * s4v[0][1];
            *reinterpret_cast<float2*>(hxo + (size_t)i0 * HXS + j0) = make_float2(x0, x1);
            *reinterpret_cast<float2*>(hyo + (size_t)i0 * HYS + j0) = make_float2(y0, y1);
            *reinterpret_cast<float2*>(hpo + (size_t)i0 * PHY + j0) = make_float2(y0, y1);
        }
        {
            const int i = i0 + 1;
            float hyv[2];
            ldrow<1, V>(hyv, hyp + (size_t)i * HYI + j0);
            float2 hxp = *reinterpret_cast<const float2*>(hx + (size_t)i * HXS + j0);
            const float x0 = hxp.x - CFLc * s3v[1][0];
            const float x1 = hxp.y - CFLc * s3v[1][1];
            const float y0 = hyv[0] + CFLc * s4v[1][0];
            const float y1 = hyv[1] + CFLc * s4v[1][1];
            *reinterpret_cast<float2*>(hxo + (size_t)i * HXS + j0) = make_float2(x0, x1);
            hyo[(size_t)i * HYS + j0]     = y0;
            hyo[(size_t)i * HYS + j0 + 1] = y1;
            *reinterpret_cast<float2*>(hpo + (size_t)i * PHY + j0) = make_float2(y0, y1);
        }
        return;
    }

    // ---- generic path (edges) ----
#define EEg(rr,cc) ein[(rr) * PE + (cc)]
    for (int rr = 0; rr < 2; rr++) {
        const int i = i0 + rr;
        if (i >= NN) break;
#pragma unroll
        for (int q = 0; q < 2; q++) {
            const int j = j0 + q;
            if (j >= NN) break;

            if (i <= NN - 2) {
                float s3 = 0.0f;
                if (j >= 1 && j <= NN - 2) {
                    s3 += -u  * EEg(i  , j-1) + c01 * EEg(i  , j) + u * EEg(i  , j+1) - u * EEg(i  , j+2)
                        + c11 * EEg(i+1, j)
                        + u   * EEg(i+2, j-1) + c21 * EEg(i+2, j) - u * EEg(i+2, j+1) + u * EEg(i+2, j+2);
                }
                if (i <= NN - 4)
                    s3 += -1.5f * EEg(i+1, j) + 2.0f * EEg(i+2, j) - 0.5f * EEg(i+3, j);
                if (i >= 2)
                    s3 +=  0.5f * EEg(i-1, j+1) - 2.0f * EEg(i, j+1) + 1.5f * EEg(i+1, j+1);
                hxo[(size_t)i * HXS + j] = hx[(size_t)i * HXS + j] - CFLc * s3;
            }

            if (j <= NN - 2) {
                float s4 = 0.0f;
                if (i >= 1 && i <= NN - 2) {
                    s4 += -u  * EEg(i-1, j) + u * EEg(i-1, j+2)
                        + c01 * EEg(i  , j) + c11 * EEg(i, j+1) + c21 * EEg(i, j+2)
                        + u   * EEg(i+1, j) - u * EEg(i+1, j+2)
                        - u   * EEg(i+2, j) + u * EEg(i+2, j+2);
                }
                if (j <= NN - 4)
                    s4 += -1.5f * EEg(i, j+1) + 2.0f * EEg(i, j+2) - 0.5f * EEg(i, j+3);
                if (j >= 2)
                    s4 +=  0.5f * EEg(i+1, j-1) - 2.0f * EEg(i+1, j) + 1.5f * EEg(i+1, j+1);
                const float val = hyp[(size_t)i * HYI + j] + CFLc * s4;
                hyo[(size_t)i * HYS + j] = val;
                hpo[(size_t)i * PHY + j] = val;
            }
        }
    }
#undef EEg
}

// ---------------------------------------------------------------------------
extern "C" void kernel_launch(void* const* d_in, const int* in_sizes, int n_in,
                              void* d_out, int out_size)
{
    const float* E0    = (const float*)d_in[0];
    const float* Hx0   = (const float*)d_in[1];
    const float* Hy0   = (const float*)d_in[2];
    const float* beta  = (const float*)d_in[3];
    const float* delta = (const float*)d_in[4];
    const float* gamma = (const float*)d_in[5];

    float* out = (float*)d_out;
    const size_t esz  = (size_t)BB * ESZ;
    const size_t hxsz = (size_t)BB * HXSZ;
    const size_t hysz = (size_t)BB * HYSZ;

    float* E2  = out;
    float* Hx2 = E2  + esz;
    float* Hy2 = Hx2 + hxsz;
    float* E3  = Hy2 + hysz;
    float* Hx3 = E3  + esz;
    float* Hy3 = Hx3 + hxsz;
    float* E4  = Hy3 + hysz;
    float* Hx4 = E4  + esz;
    float* Hy4 = Hx4 + hxsz;

    float *EA, *EB, *HA, *HB;
    cudaGetSymbolAddress((void**)&EA, g_EpadA);
    cudaGetSymbolAddress((void**)&EB, g_EpadB);
    cudaGetSymbolAddress((void**)&HA, g_HyA);
    cudaGetSymbolAddress((void**)&HB, g_HyB);

    coef_kernel<<<1, 1>>>(beta, delta, gamma);

    dim3 blk(64, 4, 1);
    dim3 gE(17, (ES + 7) / 8, BB);   // 17 x 257 x 2
    dim3 gF(16, NN / 8, BB);         // 16 x 256 x 2

    // step 1 — raw inputs, no repack
    amper_kernel<true>   <<<gE, blk>>>(E0, Hx0, Hy0, E2, EB);
    faraday_kernel<true> <<<gF, blk>>>(EB, Hx0, Hy0, Hx2, Hy2, HB);
    // step 2 — padded inputs
    amper_kernel<false>  <<<gE, blk>>>(EB, Hx2, HB, E3, EA);
    faraday_kernel<false><<<gF, blk>>>(EA, Hx2, HB, Hx3, Hy3, HA);
    // step 3
    amper_kernel<false>  <<<gE, blk>>>(EA, Hx3, HA, E4, EB);
    faraday_kernel<false><<<gF, blk>>>(EB, Hx3, HA, Hx4, Hy4, HB);
}

// round 15
// speedup vs baseline: 1.0705x; 1.0296x over previous
#include <cuda_runtime.h>

// DRP_LAYER: 2D DRP-FDTD, 3 steps, B=2, N=2048.
// R15: no padded scratch at all. All kernels read E/Hy raw from the previous
// step's d_out slices (scalar coalesced loads) and store ONLY to d_out.
// 2-row merged buffers, Hx float2 loads, __launch_bounds__(256,6).

#define NN   2048
#define BB   2
#define CFLc 0.35f

#define ES   (NN + 1)
#define HXS  (NN)
#define HYS  (NN - 1)
#define ESZ  ((NN + 1) * (NN + 1))
#define HXSZ ((NN - 1) * NN)
#define HYSZ (NN * (NN - 1))

__device__ float g_coef[2];

__global__ void coef_kernel(const float* __restrict__ beta,
                            const float* __restrict__ delta,
                            const float* __restrict__ gamma) {
    g_coef[0] = 0.25f * beta[0] - 0.1f * gamma[0];
    g_coef[1] = delta[0];
}

#define KF0 (-11.0f/6.0f)
#define KF1 (3.0f)
#define KF2 (-1.5f)
#define KF3 (1.0f/3.0f)
#define KB0 (-1.0f/3.0f)
#define KB1 (1.5f)
#define KB2 (-3.0f)
#define KB3 (11.0f/6.0f)

// Scalar span load (coalesced across warp; alignment-indifferent).
template<int NF>
__device__ __forceinline__ void ldrow_s(float* dst, const float* p) {
#pragma unroll
    for (int k = 0; k < NF; k++) dst[k] = p[k];
}
// Aligned float2 span load (Hx only; even stride, even offsets).
template<int NP>
__device__ __forceinline__ void ldrow_v(float* dst, const float* p) {
    const float2* q = reinterpret_cast<const float2*>(p);
#pragma unroll
    for (int k = 0; k < NP; k++) { float2 v = q[k]; dst[2*k] = v.x; dst[2*k+1] = v.y; }
}

// ---------------------------------------------------------------------------
// Ampere: E_out = E + CFL*(s1 - s2).
// Block (64,4): thread = col pair j0 = jb+2tx, rows r = R0+2ty, r+1.
// ---------------------------------------------------------------------------
__global__ __launch_bounds__(256, 6) void amper_kernel(
    const float* __restrict__ E, const float* __restrict__ Hx,
    const float* __restrict__ Hy, float* __restrict__ Eo)
{
    const int jb = blockIdx.x * 128;
    const int R0 = blockIdx.y * 8;
    const int tx = threadIdx.x;
    const int r  = R0 + threadIdx.y * 2;
    const int j0 = jb + 2 * tx;
    const int b  = blockIdx.z;

    const float* __restrict__ ein = E  + (size_t)b * ESZ;
    const float* __restrict__ hx  = Hx + (size_t)b * HXSZ;
    const float* __restrict__ hyp = Hy + (size_t)b * HYSZ;
    float* __restrict__ eo = Eo + (size_t)b * ESZ;

    const float u  = g_coef[0];
    const float dl = g_coef[1];
    const float c01 = u + dl - 0.5f;
    const float c11 = -2.0f * dl;
    const float c21 = dl + 0.5f - u;
    const float cKF = c21 + KF0;
    const float cKB = u + KB3;

    const bool fast = (R0 >= 8) && (R0 + 7 <= NN - 5) &&
                      (jb >= 128) && (jb + 127 <= NN - 5);

    if (fast) {
        float acc[2][2];

        // ---- Hy rows r-2..r+2, merged spans (raw stride, scalar loads) ----
        {
            float hm2[4], hm1[8], h0[12], hp1[8], hp2[4];
            ldrow_s<4> (hm2, hyp + (r-2) * HYS + (j0-2));
            ldrow_s<8> (hm1, hyp + (r-1) * HYS + (j0-2));
            ldrow_s<12>(h0 , hyp + (r  ) * HYS + (j0-6));
            ldrow_s<8> (hp1, hyp + (r+1) * HYS + (j0-6));
            ldrow_s<4> (hp2, hyp + (r+2) * HYS + (j0-2));
#pragma unroll
            for (int q = 0; q < 2; q++) {
                acc[0][q] =
                      -u * hm2[q] + u * hm2[q+2]
                    + c01 * hm1[q] + c11 * hm1[q+1] + cKF * hm1[q+2]
                    + KF1 * hm1[q+3] + KF2 * hm1[q+4] + KF3 * hm1[q+5]
                    + KB0 * h0[q+1] + KB1 * h0[q+2] + KB2 * h0[q+3]
                    + cKB * h0[q+4] - u * h0[q+6]
                    - u * hp1[q+4] + u * hp1[q+6];
                acc[1][q] =
                      -u * hm1[q] + u * hm1[q+2]
                    + c01 * h0[q+4] + c11 * h0[q+5] + cKF * h0[q+6]
                    + KF1 * h0[q+7] + KF2 * h0[q+8] + KF3 * h0[q+9]
                    + KB0 * hp1[q+1] + KB1 * hp1[q+2] + KB2 * hp1[q+3]
                    + cKB * hp1[q+4] - u * hp1[q+6]
                    - u * hp2[q] + u * hp2[q+2];
            }
        }

        // ---- Hx rows r-5..r+4, merged spans (even stride -> f2 loads) ----
        {
            float a5[2], a4[2], a3[2], a2[6], a1[6], a0[6], b1[6], b2[4], b3[4], b4[4];
            ldrow_v<1>(a5, hx + (r-5) * HXS + j0);
            ldrow_v<1>(a4, hx + (r-4) * HXS + j0);
            ldrow_v<1>(a3, hx + (r-3) * HXS + j0);
            ldrow_v<3>(a2, hx + (r-2) * HXS + (j0-2));
            ldrow_v<3>(a1, hx + (r-1) * HXS + (j0-2));
            ldrow_v<3>(a0, hx + (r  ) * HXS + (j0-2));
            ldrow_v<3>(b1, hx + (r+1) * HXS + (j0-2));
            ldrow_v<2>(b2, hx + (r+2) * HXS + (j0-2));
            ldrow_v<2>(b3, hx + (r+3) * HXS + (j0-2));
            ldrow_v<2>(b4, hx + (r+4) * HXS + (j0-2));
#pragma unroll
            for (int q = 0; q < 2; q++) {
                acc[0][q] -=
                      KB0 * a5[q] + KB1 * a4[q] + KB2 * a3[q]
                    - u * a2[q] + c01 * a2[q+1] + cKB * a2[q+2] - u * a2[q+3]
                    + c11 * a1[q+1]
                    + u * a0[q] + cKF * a0[q+1] - u * a0[q+2] + u * a0[q+3]
                    + KF1 * b1[q+1] + KF2 * b2[q+1] + KF3 * b3[q+1];
                acc[1][q] -=
                      KB0 * a4[q] + KB1 * a3[q] + KB2 * a2[q+2]
                    - u * a1[q] + c01 * a1[q+1] + cKB * a1[q+2] - u * a1[q+3]
                    + c11 * a0[q+1]
                    + u * b1[q] + cKF * b1[q+1] - u * b1[q+2] + u * b1[q+3]
                    + KF1 * b2[q+1] + KF2 * b3[q+1] + KF3 * b4[q+1];
            }
        }

        // ---- epilogue: single store stream to d_out ----
#pragma unroll
        for (int rr = 0; rr < 2; rr++) {
            const int i = r + rr;
            float ev[2];
            ldrow_s<2>(ev, ein + (size_t)i * ES + j0);
            eo[(size_t)i * ES + j0]     = ev[0] + CFLc * acc[rr][0];
            eo[(size_t)i * ES + j0 + 1] = ev[1] + CFLc * acc[rr][1];
        }
        return;
    }

    // ---- generic path (edges) ----
#define HXg(rr,cc) hx[(rr) * HXS + (cc)]
#define HYg(rr,cc) hyp[(rr) * HYS + (cc)]
    for (int rr = 0; rr < 2; rr++) {
        const int i = r + rr;
        if (i > NN) break;
#pragma unroll
        for (int q = 0; q < 2; q++) {
            const int j = j0 + q;
            if (j > NN) break;

            const bool iin = (i >= 2) && (i <= NN - 2);
            const bool jin = (j >= 2) && (j <= NN - 2);

            float s1 = 0.0f;
            if (iin && jin) {
                s1 += -u  * HYg(i-2, j-2) + u   * HYg(i-2, j)
                    + c01 * HYg(i-1, j-2) + c11 * HYg(i-1, j-1) + c21 * HYg(i-1, j)
                    + u   * HYg(i  , j-2) - u   * HYg(i  , j)
                    - u   * HYg(i+1, j-2) + u   * HYg(i+1, j);
            }
            if (i >= 1 && j <= NN - 5)
                s1 += KF0*HYg(i-1, j) + KF1*HYg(i-1, j+1) + KF2*HYg(i-1, j+2) + KF3*HYg(i-1, j+3);
            if (i <= NN - 1 && j >= 5)
                s1 += KB0*HYg(i, j-5) + KB1*HYg(i, j-4) + KB2*HYg(i, j-3) + KB3*HYg(i, j-2);
            if (iin && (j == 1 || j == 2))
                s1 += -HYg(i-1, j-1) + 3.0f*HYg(i-1, j) - 3.0f*HYg(i-1, j+1) + HYg(i-1, j+2);
            if (iin && (j == NN-2 || j == NN-1))
                s1 += HYg(i, j-4) - 3.0f*HYg(i, j-3) + 3.0f*HYg(i, j-2) - HYg(i, j-1);

            float s2 = 0.0f;
            if (iin && jin) {
                s2 += -u  * HXg(i-2, j-2) + c01 * HXg(i-2, j-1) + u * HXg(i-2, j) - u * HXg(i-2, j+1)
                    + c11 * HXg(i-1, j-1)
                    + u   * HXg(i  , j-2) + c21 * HXg(i  , j-1) - u * HXg(i  , j) + u * HXg(i  , j+1);
            }
            if (i <= NN - 5 && j >= 1)
                s2 += KF0*HXg(i, j-1) + KF1*HXg(i+1, j-1) + KF2*HXg(i+2, j-1) + KF3*HXg(i+3, j-1);
            if (i >= 5 && j <= NN - 1)
                s2 += KB0*HXg(i-5, j) + KB1*HXg(i-4, j) + KB2*HXg(i-3, j) + KB3*HXg(i-2, j);
            if ((i == 1 || i == 2) && jin)
                s2 += -HXg(i-1, j-1) + 3.0f*HXg(i, j-1) - 3.0f*HXg(i+1, j-1) + HXg(i+2, j-1);
            if ((i == NN-2 || i == NN-1) && jin)
                s2 += HXg(i-4, j) - 3.0f*HXg(i-3, j) + 3.0f*HXg(i-2, j) - HXg(i-1, j);

            eo[(size_t)i * ES + j] = ein[(size_t)i * ES + j] + CFLc * (s1 - s2);
        }
    }
#undef HXg
#undef HYg
}

// ---------------------------------------------------------------------------
// Faraday: Hx_out = Hx - CFL*s3 ; Hy_out = Hy + CFL*s4
// Block (64,4): thread = col pair j0, rows i = R0+2ty (even), i+1.
// E read raw from d_out (scalar loads).
// ---------------------------------------------------------------------------
__global__ __launch_bounds__(256, 6) void faraday_kernel(
    const float* __restrict__ E, const float* __restrict__ Hx,
    const float* __restrict__ Hy,
    float* __restrict__ Hxo, float* __restrict__ Hyo)
{
    const int jb = blockIdx.x * 128;
    const int R0 = blockIdx.y * 8;
    const int tx = threadIdx.x;
    const int i0 = R0 + threadIdx.y * 2;
    const int j0 = jb + 2 * tx;
    const int b  = blockIdx.z;

    const float* __restrict__ ein = E  + (size_t)b * ESZ;
    const float* __restrict__ hx  = Hx + (size_t)b * HXSZ;
    const float* __restrict__ hyp = Hy + (size_t)b * HYSZ;
    float* __restrict__ hxo = Hxo + (size_t)b * HXSZ;
    float* __restrict__ hyo = Hyo + (size_t)b * HYSZ;

    const float u  = g_coef[0];
    const float dl = g_coef[1];
    const float c01 = u + dl - 0.5f;
    const float c11 = -2.0f * dl;
    const float c21 = dl + 0.5f - u;

    const bool fast = (R0 >= 8) && (R0 + 7 <= NN - 4) &&
                      (jb >= 128) && (jb + 127 <= NN - 4);

    if (fast) {
        float fm1[4], f0[8], f1[8], f2[6], f3[6], f4[2];
        ldrow_s<4>(fm1, ein + (size_t)(i0-1) * ES + j0);
        ldrow_s<8>(f0 , ein + (size_t)(i0  ) * ES + (j0-2));
        ldrow_s<8>(f1 , ein + (size_t)(i0+1) * ES + (j0-2));
        ldrow_s<6>(f2 , ein + (size_t)(i0+2) * ES + (j0-2));
        ldrow_s<6>(f3 , ein + (size_t)(i0+3) * ES + (j0-2));
        ldrow_s<2>(f4 , ein + (size_t)(i0+4) * ES + j0);

        float s3v[2][2], s4v[2][2];
#pragma unroll
        for (int q = 0; q < 2; q++) {
            s3v[0][q] = 0.5f * fm1[q+1]
                      - u * f0[q+1] + c01 * f0[q+2] + (u - 2.0f) * f0[q+3] - u * f0[q+4]
                      + (c11 - 1.5f) * f1[q+2] + 1.5f * f1[q+3]
                      + u * f2[q+1] + (c21 + 2.0f) * f2[q+2] - u * f2[q+3] + u * f2[q+4]
                      - 0.5f * f3[q+2];
            s4v[0][q] = -u * fm1[q] + u * fm1[q+2]
                      + c01 * f0[q+2] + (c11 - 1.5f) * f0[q+3]
                      + (c21 + 2.0f) * f0[q+4] - 0.5f * f0[q+5]
                      + 0.5f * f1[q+1] + (u - 2.0f) * f1[q+2] + 1.5f * f1[q+3] - u * f1[q+4]
                      - u * f2[q+2] + u * f2[q+4];
            s3v[1][q] = 0.5f * f0[q+3]
                      - u * f1[q+1] + c01 * f1[q+2] + (u - 2.0f) * f1[q+3] - u * f1[q+4]
                      + (c11 - 1.5f) * f2[q+2] + 1.5f * f2[q+3]
                      + u * f3[q+1] + (c21 + 2.0f) * f3[q+2] - u * f3[q+3] + u * f3[q+4]
                      - 0.5f * f4[q];
            s4v[1][q] = -u * f0[q+2] + u * f0[q+4]
                      + c01 * f1[q+2] + (c11 - 1.5f) * f1[q+3]
                      + (c21 + 2.0f) * f1[q+4] - 0.5f * f1[q+5]
                      + 0.5f * f2[q+1] + (u - 2.0f) * f2[q+2] + 1.5f * f2[q+3] - u * f2[q+4]
                      - u * f3[q+2] + u * f3[q+4];
        }

        // row i0 (even): hyo f2 store aligned (HYSZ, i0*HYS, j0 all even)
        {
            float hyv[2];
            ldrow_s<2>(hyv, hyp + (size_t)i0 * HYS + j0);
            float2 hxp = *reinterpret_cast<const float2*>(hx + (size_t)i0 * HXS + j0);
            const float x0 = hxp.x - CFLc * s3v[0][0];
            const float x1 = hxp.y - CFLc * s3v[0][1];
            const float y0 = hyv[0] + CFLc * s4v[0][0];
            const float y1 = hyv[1] + CFLc * s4v[0][1];
            *reinterpret_cast<float2*>(hxo + (size_t)i0 * HXS + j0) = make_float2(x0, x1);
            *reinterpret_cast<float2*>(hyo + (size_t)i0 * HYS + j0) = make_float2(y0, y1);
        }
        {
            const int i = i0 + 1;
            float hyv[2];
            ldrow_s<2>(hyv, hyp + (size_t)i * HYS + j0);
            float2 hxp = *reinterpret_cast<const float2*>(hx + (size_t)i * HXS + j0);
            const float x0 = hxp.x - CFLc * s3v[1][0];
            const float x1 = hxp.y - CFLc * s3v[1][1];
            *reinterpret_cast<float2*>(hxo + (size_t)i * HXS + j0) = make_float2(x0, x1);
            hyo[(size_t)i * HYS + j0]     = hyv[0] + CFLc * s4v[1][0];
            hyo[(size_t)i * HYS + j0 + 1] = hyv[1] + CFLc * s4v[1][1];
        }
        return;
    }

    // ---- generic path (edges) ----
#define EEg(rr,cc) ein[(rr) * ES + (cc)]
    for (int rr = 0; rr < 2; rr++) {
        const int i = i0 + rr;
        if (i >= NN) break;
#pragma unroll
        for (int q = 0; q < 2; q++) {
            const int j = j0 + q;
            if (j >= NN) break;

            if (i <= NN - 2) {
                float s3 = 0.0f;
                if (j >= 1 && j <= NN - 2) {
                    s3 += -u  * EEg(i  , j-1) + c01 * EEg(i  , j) + u * EEg(i  , j+1) - u * EEg(i  , j+2)
                        + c11 * EEg(i+1, j)
                        + u   * EEg(i+2, j-1) + c21 * EEg(i+2, j) - u * EEg(i+2, j+1) + u * EEg(i+2, j+2);
                }
                if (i <= NN - 4)
                    s3 += -1.5f * EEg(i+1, j) + 2.0f * EEg(i+2, j) - 0.5f * EEg(i+3, j);
                if (i >= 2)
                    s3 +=  0.5f * EEg(i-1, j+1) - 2.0f * EEg(i, j+1) + 1.5f * EEg(i+1, j+1);
                hxo[(size_t)i * HXS + j] = hx[(size_t)i * HXS + j] - CFLc * s3;
            }

            if (j <= NN - 2) {
                float s4 = 0.0f;
                if (i >= 1 && i <= NN - 2) {
                    s4 += -u  * EEg(i-1, j) + u * EEg(i-1, j+2)
                        + c01 * EEg(i  , j) + c11 * EEg(i, j+1) + c21 * EEg(i, j+2)
                        + u   * EEg(i+1, j) - u * EEg(i+1, j+2)
                        - u   * EEg(i+2, j) + u * EEg(i+2, j+2);
                }
                if (j <= NN - 4)
                    s4 += -1.5f * EEg(i, j+1) + 2.0f * EEg(i, j+2) - 0.5f * EEg(i, j+3);
                if (j >= 2)
                    s4 +=  0.5f * EEg(i+1, j-1) - 2.0f * EEg(i+1, j) + 1.5f * EEg(i+1, j+1);
                hyo[(size_t)i * HYS + j] = hyp[(size_t)i * HYS + j] + CFLc * s4;
            }
        }
    }
#undef EEg
}

// ---------------------------------------------------------------------------
extern "C" void kernel_launch(void* const* d_in, const int* in_sizes, int n_in,
                              void* d_out, int out_size)
{
    const float* E0    = (const float*)d_in[0];
    const float* Hx0   = (const float*)d_in[1];
    const float* Hy0   = (const float*)d_in[2];
    const float* beta  = (const float*)d_in[3];
    const float* delta = (const float*)d_in[4];
    const float* gamma = (const float*)d_in[5];

    float* out = (float*)d_out;
    const size_t esz  = (size_t)BB * ESZ;
    const size_t hxsz = (size_t)BB * HXSZ;
    const size_t hysz = (size_t)BB * HYSZ;

    float* E2  = out;
    float* Hx2 = E2  + esz;
    float* Hy2 = Hx2 + hxsz;
    float* E3  = Hy2 + hysz;
    float* Hx3 = E3  + esz;
    float* Hy3 = Hx3 + hxsz;
    float* E4  = Hy3 + hysz;
    float* Hx4 = E4  + esz;
    float* Hy4 = Hx4 + hxsz;

    coef_kernel<<<1, 1>>>(beta, delta, gamma);

    dim3 blk(64, 4, 1);
    dim3 gE(17, (ES + 7) / 8, BB);   // 17 x 257 x 2
    dim3 gF(16, NN / 8, BB);         // 16 x 256 x 2

    // step 1
    amper_kernel  <<<gE, blk>>>(E0, Hx0, Hy0, E2);
    faraday_kernel<<<gF, blk>>>(E2, Hx0, Hy0, Hx2, Hy2);
    // step 2
    amper_kernel  <<<gE, blk>>>(E2, Hx2, Hy2, E3);
    faraday_kernel<<<gF, blk>>>(E3, Hx2, Hy2, Hx3, Hy3);
    // step 3
    amper_kernel  <<<gE, blk>>>(E3, Hx3, Hy3, E4);
    faraday_kernel<<<gF, blk>>>(E4, Hx3, Hy3, Hx4, Hy4);
}

// round 16
// speedup vs baseline: 1.1682x; 1.0913x over previous
#include <cuda_runtime.h>

// DRP_LAYER: 2D DRP-FDTD, 3 steps, B=2, N=2048.
// R16: parity-static float2 loads on raw odd-stride arrays.
// Rows at even i have even base-offset parity (f2-aligned); odd rows are
// f2-aligned from d-1. E parity depends on batch (ESZ odd) -> faraday fast
// path templated on PB = b&1. Single store stream to d_out (R15).

#define NN   2048
#define BB   2
#define CFLc 0.35f

#define ES   (NN + 1)
#define HXS  (NN)
#define HYS  (NN - 1)
#define ESZ  ((NN + 1) * (NN + 1))
#define HXSZ ((NN - 1) * NN)
#define HYSZ (NN * (NN - 1))

__device__ float g_coef[2];

__global__ void coef_kernel(const float* __restrict__ beta,
                            const float* __restrict__ delta,
                            const float* __restrict__ gamma) {
    g_coef[0] = 0.25f * beta[0] - 0.1f * gamma[0];
    g_coef[1] = delta[0];
}

#define KF0 (-11.0f/6.0f)
#define KF1 (3.0f)
#define KF2 (-1.5f)
#define KF3 (1.0f/3.0f)
#define KB0 (-1.0f/3.0f)
#define KB1 (1.5f)
#define KB2 (-3.0f)
#define KB3 (11.0f/6.0f)

template<int NF>
__device__ __forceinline__ void ldrow_s(float* dst, const float* p) {
#pragma unroll
    for (int k = 0; k < NF; k++) dst[k] = p[k];
}
template<int NP>
__device__ __forceinline__ void ldrow_v(float* dst, const float* p) {
    const float2* q = reinterpret_cast<const float2*>(p);
#pragma unroll
    for (int k = 0; k < NP; k++) { float2 v = q[k]; dst[2*k] = v.x; dst[2*k+1] = v.y; }
}

// ---------------------------------------------------------------------------
// Ampere: E_out = E + CFL*(s1 - s2).
// Block (64,4): col pair j0 = jb+2tx, rows r (even), r+1.
// Hy parity is batch-invariant (HYSZ even): rows r-2,r,r+2 even; r-1,r+1 odd.
// ---------------------------------------------------------------------------
__global__ __launch_bounds__(256, 6) void amper_kernel(
    const float* __restrict__ E, const float* __restrict__ Hx,
    const float* __restrict__ Hy, float* __restrict__ Eo)
{
    const int jb = blockIdx.x * 128;
    const int R0 = blockIdx.y * 8;
    const int tx = threadIdx.x;
    const int r  = R0 + threadIdx.y * 2;
    const int j0 = jb + 2 * tx;
    const int b  = blockIdx.z;

    const float* __restrict__ ein = E  + (size_t)b * ESZ;
    const float* __restrict__ hx  = Hx + (size_t)b * HXSZ;
    const float* __restrict__ hyp = Hy + (size_t)b * HYSZ;
    float* __restrict__ eo = Eo + (size_t)b * ESZ;

    const float u  = g_coef[0];
    const float dl = g_coef[1];
    const float c01 = u + dl - 0.5f;
    const float c11 = -2.0f * dl;
    const float c21 = dl + 0.5f - u;
    const float cKF = c21 + KF0;
    const float cKB = u + KB3;

    const bool fast = (R0 >= 8) && (R0 + 7 <= NN - 5) &&
                      (jb >= 128) && (jb + 127 <= NN - 5);

    if (fast) {
        float acc[2][2];

        // ---- Hy rows r-2..r+2: parity-static f2 loads ----
        // origins: hm2 -2 (even), hm1 -3 (odd), h0 -6 (even), hp1 -5 (odd), hp2 -2 (even)
        {
            float hm2[4], hm1[8], h0[12], hp1[8], hp2[4];
            ldrow_v<2>(hm2, hyp + (size_t)(r-2) * HYS + (j0-2));
            ldrow_v<4>(hm1, hyp + (size_t)(r-1) * HYS + (j0-3));
            ldrow_v<6>(h0 , hyp + (size_t)(r  ) * HYS + (j0-6));
            ldrow_v<4>(hp1, hyp + (size_t)(r+1) * HYS + (j0-5));
            ldrow_v<2>(hp2, hyp + (size_t)(r+2) * HYS + (j0-2));
#pragma unroll
            for (int q = 0; q < 2; q++) {
                // row r
                acc[0][q] =
                      -u * hm2[q] + u * hm2[q+2]
                    + c01 * hm1[q+1] + c11 * hm1[q+2] + cKF * hm1[q+3]
                    + KF1 * hm1[q+4] + KF2 * hm1[q+5] + KF3 * hm1[q+6]
                    + KB0 * h0[q+1] + KB1 * h0[q+2] + KB2 * h0[q+3]
                    + cKB * h0[q+4] - u * h0[q+6]
                    - u * hp1[q+3] + u * hp1[q+5];
                // row r+1
                acc[1][q] =
                      -u * hm1[q+1] + u * hm1[q+3]
                    + c01 * h0[q+4] + c11 * h0[q+5] + cKF * h0[q+6]
                    + KF1 * h0[q+7] + KF2 * h0[q+8] + KF3 * h0[q+9]
                    + KB0 * hp1[q] + KB1 * hp1[q+1] + KB2 * hp1[q+2]
                    + cKB * hp1[q+3] - u * hp1[q+5]
                    - u * hp2[q] + u * hp2[q+2];
            }
        }

        // ---- Hx rows r-5..r+4: even stride, f2 loads (unchanged) ----
        {
            float a5[2], a4[2], a3[2], a2[6], a1[6], a0[6], b1[6], b2[4], b3[4], b4[4];
            ldrow_v<1>(a5, hx + (size_t)(r-5) * HXS + j0);
            ldrow_v<1>(a4, hx + (size_t)(r-4) * HXS + j0);
            ldrow_v<1>(a3, hx + (size_t)(r-3) * HXS + j0);
            ldrow_v<3>(a2, hx + (size_t)(r-2) * HXS + (j0-2));
            ldrow_v<3>(a1, hx + (size_t)(r-1) * HXS + (j0-2));
            ldrow_v<3>(a0, hx + (size_t)(r  ) * HXS + (j0-2));
            ldrow_v<3>(b1, hx + (size_t)(r+1) * HXS + (j0-2));
            ldrow_v<2>(b2, hx + (size_t)(r+2) * HXS + (j0-2));
            ldrow_v<2>(b3, hx + (size_t)(r+3) * HXS + (j0-2));
            ldrow_v<2>(b4, hx + (size_t)(r+4) * HXS + (j0-2));
#pragma unroll
            for (int q = 0; q < 2; q++) {
                acc[0][q] -=
                      KB0 * a5[q] + KB1 * a4[q] + KB2 * a3[q]
                    - u * a2[q] + c01 * a2[q+1] + cKB * a2[q+2] - u * a2[q+3]
                    + c11 * a1[q+1]
                    + u * a0[q] + cKF * a0[q+1] - u * a0[q+2] + u * a0[q+3]
                    + KF1 * b1[q+1] + KF2 * b2[q+1] + KF3 * b3[q+1];
                acc[1][q] -=
                      KB0 * a4[q] + KB1 * a3[q] + KB2 * a2[q+2]
                    - u * a1[q] + c01 * a1[q+1] + cKB * a1[q+2] - u * a1[q+3]
                    + c11 * a0[q+1]
                    + u * b1[q] + cKF * b1[q+1] - u * b1[q+2] + u * b1[q+3]
                    + KF1 * b2[q+1] + KF2 * b3[q+1] + KF3 * b4[q+1];
            }
        }

        // ---- epilogue (E parity batch-dependent -> scalar) ----
#pragma unroll
        for (int rr = 0; rr < 2; rr++) {
            const int i = r + rr;
            float ev[2];
            ldrow_s<2>(ev, ein + (size_t)i * ES + j0);
            eo[(size_t)i * ES + j0]     = ev[0] + CFLc * acc[rr][0];
            eo[(size_t)i * ES + j0 + 1] = ev[1] + CFLc * acc[rr][1];
        }
        return;
    }

    // ---- generic path (edges) ----
#define HXg(rr,cc) hx[(rr) * HXS + (cc)]
#define HYg(rr,cc) hyp[(rr) * HYS + (cc)]
    for (int rr = 0; rr < 2; rr++) {
        const int i = r + rr;
        if (i > NN) break;
#pragma unroll
        for (int q = 0; q < 2; q++) {
            const int j = j0 + q;
            if (j > NN) break;

            const bool iin = (i >= 2) && (i <= NN - 2);
            const bool jin = (j >= 2) && (j <= NN - 2);

            float s1 = 0.0f;
            if (iin && jin) {
                s1 += -u  * HYg(i-2, j-2) + u   * HYg(i-2, j)
                    + c01 * HYg(i-1, j-2) + c11 * HYg(i-1, j-1) + c21 * HYg(i-1, j)
                    + u   * HYg(i  , j-2) - u   * HYg(i  , j)
                    - u   * HYg(i+1, j-2) + u   * HYg(i+1, j);
            }
            if (i >= 1 && j <= NN - 5)
                s1 += KF0*HYg(i-1, j) + KF1*HYg(i-1, j+1) + KF2*HYg(i-1, j+2) + KF3*HYg(i-1, j+3);
            if (i <= NN - 1 && j >= 5)
                s1 += KB0*HYg(i, j-5) + KB1*HYg(i, j-4) + KB2*HYg(i, j-3) + KB3*HYg(i, j-2);
            if (iin && (j == 1 || j == 2))
                s1 += -HYg(i-1, j-1) + 3.0f*HYg(i-1, j) - 3.0f*HYg(i-1, j+1) + HYg(i-1, j+2);
            if (iin && (j == NN-2 || j == NN-1))
                s1 += HYg(i, j-4) - 3.0f*HYg(i, j-3) + 3.0f*HYg(i, j-2) - HYg(i, j-1);

            float s2 = 0.0f;
            if (iin && jin) {
                s2 += -u  * HXg(i-2, j-2) + c01 * HXg(i-2, j-1) + u * HXg(i-2, j) - u * HXg(i-2, j+1)
                    + c11 * HXg(i-1, j-1)
                    + u   * HXg(i  , j-2) + c21 * HXg(i  , j-1) - u * HXg(i  , j) + u * HXg(i  , j+1);
            }
            if (i <= NN - 5 && j >= 1)
                s2 += KF0*HXg(i, j-1) + KF1*HXg(i+1, j-1) + KF2*HXg(i+2, j-1) + KF3*HXg(i+3, j-1);
            if (i >= 5 && j <= NN - 1)
                s2 += KB0*HXg(i-5, j) + KB1*HXg(i-4, j) + KB2*HXg(i-3, j) + KB3*HXg(i-2, j);
            if ((i == 1 || i == 2) && jin)
                s2 += -HXg(i-1, j-1) + 3.0f*HXg(i, j-1) - 3.0f*HXg(i+1, j-1) + HXg(i+2, j-1);
            if ((i == NN-2 || i == NN-1) && jin)
                s2 += HXg(i-4, j) - 3.0f*HXg(i-3, j) + 3.0f*HXg(i-2, j) - HXg(i-1, j);

            eo[(size_t)i * ES + j] = ein[(size_t)i * ES + j] + CFLc * (s1 - s2);
        }
    }
#undef HXg
#undef HYg
}

// ---------------------------------------------------------------------------
// Faraday fast path, templated on E parity PB = b&1.
// Row i0+k of E has offset parity (k+PB)&1; origin chosen to match.
// ---------------------------------------------------------------------------
template<int PB>
__device__ __forceinline__ void faraday_fast(
    const float* __restrict__ ein, const float* __restrict__ hx,
    const float* __restrict__ hyp,
    float* __restrict__ hxo, float* __restrict__ hyo,
    int i0, int j0, float u, float c01, float c11, float c21)
{
    constexpr int OM1 = (PB == 0) ? -1 : 0;   constexpr int NM1 = (PB == 0) ? 3 : 2;
    constexpr int O0  = (PB == 0) ? -2 : -1;  constexpr int N0  = (PB == 0) ? 4 : 3;
    constexpr int O1  = (PB == 0) ? -1 : -2;  constexpr int N1  = (PB == 0) ? 3 : 4;
    constexpr int O2  = (PB == 0) ? -2 : -1;  constexpr int N2  = 3;
    constexpr int O3  = (PB == 0) ? -1 : -2;  constexpr int N3  = 3;
    constexpr int O4  = (PB == 0) ?  0 : -1;  constexpr int N4  = (PB == 0) ? 1 : 2;

    float fm1[2*NM1], f0b[2*N0], f1b[2*N1], f2b[2*N2], f3b[2*N3], f4b[2*N4];
    ldrow_v<NM1>(fm1, ein + (size_t)(i0-1) * ES + (j0 + OM1));
    ldrow_v<N0> (f0b, ein + (size_t)(i0  ) * ES + (j0 + O0));
    ldrow_v<N1> (f1b, ein + (size_t)(i0+1) * ES + (j0 + O1));
    ldrow_v<N2> (f2b, ein + (size_t)(i0+2) * ES + (j0 + O2));
    ldrow_v<N3> (f3b, ein + (size_t)(i0+3) * ES + (j0 + O3));
    ldrow_v<N4> (f4b, ein + (size_t)(i0+4) * ES + (j0 + O4));

#define FM1(d) fm1[q + (d) - OM1]
#define F0(d)  f0b[q + (d) - O0]
#define F1(d)  f1b[q + (d) - O1]
#define F2(d)  f2b[q + (d) - O2]
#define F3(d)  f3b[q + (d) - O3]
#define F4(d)  f4b[q + (d) - O4]

    float s3v[2][2], s4v[2][2];
#pragma unroll
    for (int q = 0; q < 2; q++) {
        s3v[0][q] = 0.5f * FM1(1)
                  - u * F0(-1) + c01 * F0(0) + (u - 2.0f) * F0(1) - u * F0(2)
                  + (c11 - 1.5f) * F1(0) + 1.5f * F1(1)
                  + u * F2(-1) + (c21 + 2.0f) * F2(0) - u * F2(1) + u * F2(2)
                  - 0.5f * F3(0);
        s4v[0][q] = -u * FM1(0) + u * FM1(2)
                  + c01 * F0(0) + (c11 - 1.5f) * F0(1)
                  + (c21 + 2.0f) * F0(2) - 0.5f * F0(3)
                  + 0.5f * F1(-1) + (u - 2.0f) * F1(0) + 1.5f * F1(1) - u * F1(2)
                  - u * F2(0) + u * F2(2);
        s3v[1][q] = 0.5f * F0(1)
                  - u * F1(-1) + c01 * F1(0) + (u - 2.0f) * F1(1) - u * F1(2)
                  + (c11 - 1.5f) * F2(0) + 1.5f * F2(1)
                  + u * F3(-1) + (c21 + 2.0f) * F3(0) - u * F3(1) + u * F3(2)
                  - 0.5f * F4(0);
        s4v[1][q] = -u * F0(0) + u * F0(2)
                  + c01 * F1(0) + (c11 - 1.5f) * F1(1)
                  + (c21 + 2.0f) * F1(2) - 0.5f * F1(3)
                  + 0.5f * F2(-1) + (u - 2.0f) * F2(0) + 1.5f * F2(1) - u * F2(2)
                  - u * F3(0) + u * F3(2);
    }
#undef FM1
#undef F0
#undef F1
#undef F2
#undef F3
#undef F4

    // row i0 (even Hy parity): f2 load + f2 store
    {
        float hyv[2];
        ldrow_v<1>(hyv, hyp + (size_t)i0 * HYS + j0);
        float2 hxp = *reinterpret_cast<const float2*>(hx + (size_t)i0 * HXS + j0);
        const float x0 = hxp.x - CFLc * s3v[0][0];
        const float x1 = hxp.y - CFLc * s3v[0][1];
        const float y0 = hyv[0] + CFLc * s4v[0][0];
        const float y1 = hyv[1] + CFLc * s4v[0][1];
        *reinterpret_cast<float2*>(hxo + (size_t)i0 * HXS + j0) = make_float2(x0, x1);
        *reinterpret_cast<float2*>(hyo + (size_t)i0 * HYS + j0) = make_float2(y0, y1);
    }
    // row i0+1 (odd Hy parity): scalar Hy
    {
        const int i = i0 + 1;
        float hyv[2];
        ldrow_s<2>(hyv, hyp + (size_t)i * HYS + j0);
        float2 hxp = *reinterpret_cast<const float2*>(hx + (size_t)i * HXS + j0);
        const float x0 = hxp.x - CFLc * s3v[1][0];
        const float x1 = hxp.y - CFLc * s3v[1][1];
        *reinterpret_cast<float2*>(hxo + (size_t)i * HXS + j0) = make_float2(x0, x1);
        hyo[(size_t)i * HYS + j0]     = hyv[0] + CFLc * s4v[1][0];
        hyo[(size_t)i * HYS + j0 + 1] = hyv[1] + CFLc * s4v[1][1];
    }
}

__global__ __launch_bounds__(256, 6) void faraday_kernel(
    const float* __restrict__ E, const float* __restrict__ Hx,
    const float* __restrict__ Hy,
    float* __restrict__ Hxo, float* __restrict__ Hyo)
{
    const int jb = blockIdx.x * 128;
    const int R0 = blockIdx.y * 8;
    const int tx = threadIdx.x;
    const int i0 = R0 + threadIdx.y * 2;
    const int j0 = jb + 2 * tx;
    const int b  = blockIdx.z;

    const float* __restrict__ ein = E  + (size_t)b * ESZ;
    const float* __restrict__ hx  = Hx + (size_t)b * HXSZ;
    const float* __restrict__ hyp = Hy + (size_t)b * HYSZ;
    float* __restrict__ hxo = Hxo + (size_t)b * HXSZ;
    float* __restrict__ hyo = Hyo + (size_t)b * HYSZ;

    const float u  = g_coef[0];
    const float dl = g_coef[1];
    const float c01 = u + dl - 0.5f;
    const float c11 = -2.0f * dl;
    const float c21 = dl + 0.5f - u;

    const bool fast = (R0 >= 8) && (R0 + 7 <= NN - 4) &&
                      (jb >= 128) && (jb + 127 <= NN - 4);

    if (fast) {
        if ((b & 1) == 0)
            faraday_fast<0>(ein, hx, hyp, hxo, hyo, i0, j0, u, c01, c11, c21);
        else
            faraday_fast<1>(ein, hx, hyp, hxo, hyo, i0, j0, u, c01, c11, c21);
        return;
    }

    // ---- generic path (edges) ----
#define EEg(rr,cc) ein[(rr) * ES + (cc)]
    for (int rr = 0; rr < 2; rr++) {
        const int i = i0 + rr;
        if (i >= NN) break;
#pragma unroll
        for (int q = 0; q < 2; q++) {
            const int j = j0 + q;
            if (j >= NN) break;

            if (i <= NN - 2) {
                float s3 = 0.0f;
                if (j >= 1 && j <= NN - 2) {
                    s3 += -u  * EEg(i  , j-1) + c01 * EEg(i  , j) + u * EEg(i  , j+1) - u * EEg(i  , j+2)
                        + c11 * EEg(i+1, j)
                        + u   * EEg(i+2, j-1) + c21 * EEg(i+2, j) - u * EEg(i+2, j+1) + u * EEg(i+2, j+2);
                }
                if (i <= NN - 4)
                    s3 += -1.5f * EEg(i+1, j) + 2.0f * EEg(i+2, j) - 0.5f * EEg(i+3, j);
                if (i >= 2)
                    s3 +=  0.5f * EEg(i-1, j+1) - 2.0f * EEg(i, j+1) + 1.5f * EEg(i+1, j+1);
                hxo[(size_t)i * HXS + j] = hx[(size_t)i * HXS + j] - CFLc * s3;
            }

            if (j <= NN - 2) {
                float s4 = 0.0f;
                if (i >= 1 && i <= NN - 2) {
                    s4 += -u  * EEg(i-1, j) + u * EEg(i-1, j+2)
                        + c01 * EEg(i  , j) + c11 * EEg(i, j+1) + c21 * EEg(i, j+2)
                        + u   * EEg(i+1, j) - u * EEg(i+1, j+2)
                        - u   * EEg(i+2, j) + u * EEg(i+2, j+2);
                }
                if (j <= NN - 4)
                    s4 += -1.5f * EEg(i, j+1) + 2.0f * EEg(i, j+2) - 0.5f * EEg(i, j+3);
                if (j >= 2)
                    s4 +=  0.5f * EEg(i+1, j-1) - 2.0f * EEg(i+1, j) + 1.5f * EEg(i+1, j+1);
                hyo[(size_t)i * HYS + j] = hyp[(size_t)i * HYS + j] + CFLc * s4;
            }
        }
    }
#undef EEg
}

// ---------------------------------------------------------------------------
extern "C" void kernel_launch(void* const* d_in, const int* in_sizes, int n_in,
                              void* d_out, int out_size)
{
    const float* E0    = (const float*)d_in[0];
    const float* Hx0   = (const float*)d_in[1];
    const float* Hy0   = (const float*)d_in[2];
    const float* beta  = (const float*)d_in[3];
    const float* delta = (const float*)d_in[4];
    const float* gamma = (const float*)d_in[5];

    float* out = (float*)d_out;
    const size_t esz  = (size_t)BB * ESZ;
    const size_t hxsz = (size_t)BB * HXSZ;
    const size_t hysz = (size_t)BB * HYSZ;

    float* E2  = out;
    float* Hx2 = E2  + esz;
    float* Hy2 = Hx2 + hxsz;
    float* E3  = Hy2 + hysz;
    float* Hx3 = E3  + esz;
    float* Hy3 = Hx3 + hxsz;
    float* E4  = Hy3 + hysz;
    float* Hx4 = E4  + esz;
    float* Hy4 = Hx4 + hxsz;

    coef_kernel<<<1, 1>>>(beta, delta, gamma);

    dim3 blk(64, 4, 1);
    dim3 gE(17, (ES + 7) / 8, BB);   // 17 x 257 x 2
    dim3 gF(16, NN / 8, BB);         // 16 x 256 x 2

    // step 1
    amper_kernel  <<<gE, blk>>>(E0, Hx0, Hy0, E2);
    faraday_kernel<<<gF, blk>>>(E2, Hx0, Hy0, Hx2, Hy2);
    // step 2
    amper_kernel  <<<gE, blk>>>(E2, Hx2, Hy2, E3);
    faraday_kernel<<<gF, blk>>>(E3, Hx2, Hy2, Hx3, Hy3);
    // step 3
    amper_kernel  <<<gE, blk>>>(E3, Hx3, Hy3, E4);
    faraday_kernel<<<gF, blk>>>(E4, Hx3, Hy3, Hx4, Hy4);
}

// round 17
// speedup vs baseline: 1.1799x; 1.0100x over previous
#include <cuda_runtime.h>

// DRP_LAYER: 2D DRP-FDTD, 3 steps, B=2, N=2048.
// R17: amper = 4-row scatter accumulation with parity-static f2 origins
// (rows r..r+3, r = R0+4ty even; input row parity static per offset).
// faraday = R16 (2-row, PB-templated parity f2). Stores only to d_out.

#define NN   2048
#define BB   2
#define CFLc 0.35f

#define ES   (NN + 1)
#define HXS  (NN)
#define HYS  (NN - 1)
#define ESZ  ((NN + 1) * (NN + 1))
#define HXSZ ((NN - 1) * NN)
#define HYSZ (NN * (NN - 1))

__device__ float g_coef[2];

__global__ void coef_kernel(const float* __restrict__ beta,
                            const float* __restrict__ delta,
                            const float* __restrict__ gamma) {
    g_coef[0] = 0.25f * beta[0] - 0.1f * gamma[0];
    g_coef[1] = delta[0];
}

#define KF0 (-11.0f/6.0f)
#define KF1 (3.0f)
#define KF2 (-1.5f)
#define KF3 (1.0f/3.0f)
#define KB0 (-1.0f/3.0f)
#define KB1 (1.5f)
#define KB2 (-3.0f)
#define KB3 (11.0f/6.0f)

template<int NF>
__device__ __forceinline__ void ldrow_s(float* dst, const float* p) {
#pragma unroll
    for (int k = 0; k < NF; k++) dst[k] = p[k];
}
template<int NP>
__device__ __forceinline__ void ldrow_v(float* dst, const float* p) {
    const float2* q = reinterpret_cast<const float2*>(p);
#pragma unroll
    for (int k = 0; k < NP; k++) { float2 v = q[k]; dst[2*k] = v.x; dst[2*k+1] = v.y; }
}

// ---------------------------------------------------------------------------
// Ampere: E_out = E + CFL*(s1 - s2).
// Block (64,4): col pair j0 = jb+2tx, rows r..r+3, r = R0 + 4ty (even).
// 4-row scatter: each input row loaded once with a parity-static f2 origin,
// contributions scattered into 4 accumulators (all indices static).
// ---------------------------------------------------------------------------
__global__ __launch_bounds__(256, 6) void amper_kernel(
    const float* __restrict__ E, const float* __restrict__ Hx,
    const float* __restrict__ Hy, float* __restrict__ Eo)
{
    const int jb = blockIdx.x * 128;
    const int R0 = blockIdx.y * 16;
    const int tx = threadIdx.x;
    const int r  = R0 + threadIdx.y * 4;
    const int j0 = jb + 2 * tx;
    const int b  = blockIdx.z;

    const float* __restrict__ ein = E  + (size_t)b * ESZ;
    const float* __restrict__ hx  = Hx + (size_t)b * HXSZ;
    const float* __restrict__ hyp = Hy + (size_t)b * HYSZ;
    float* __restrict__ eo = Eo + (size_t)b * ESZ;

    const float u  = g_coef[0];
    const float dl = g_coef[1];
    const float c01 = u + dl - 0.5f;
    const float c11 = -2.0f * dl;
    const float c21 = dl + 0.5f - u;
    const float cKF = c21 + KF0;
    const float cKB = u + KB3;

    const bool fast = (R0 >= 8) && (R0 + 15 <= NN - 5) &&
                      (jb >= 128) && (jb + 127 <= NN - 5);

    if (fast) {
        float acc[4][2];
#pragma unroll
        for (int o = 0; o < 4; o++) { acc[o][0] = 0.0f; acc[o][1] = 0.0f; }

        // ---- Hy rows r-2..r+4 (row r+yy has parity yy&1; origin static) ----
        // roles: M2 -> acc[yy+2], M1 -> acc[yy+1], Y0 -> acc[yy], P1 -> acc[yy-1]
#pragma unroll
        for (int yy = -2; yy <= 4; yy++) {
            const bool M2 = (yy + 2 >= 0) && (yy + 2 <= 3);
            const bool M1 = (yy + 1 >= 0) && (yy + 1 <= 3);
            const bool Y0 = (yy     >= 0) && (yy     <= 3);
            const bool P1 = (yy - 1 >= 0) && (yy - 1 <= 3);
            // span of d needed (before +q): M2/P1: [-2,0]; M1: [-2,3]; Y0: [-5,0]
            int lo_raw = Y0 ? -5 : -2;
            int hi_raw = M1 ?  4 : (Y0 ? 1 : 1);   // +q=1 included
            // parity-match origin: (yy&1)==0 -> even lo; ==1 -> odd lo
            const int lo = ((yy & 1) == 0) ? (lo_raw - (lo_raw & 1 ? 1 : 0) - ((-lo_raw) & 1)) : lo_raw;
            // simpler: choose exact static origins per yy
            int olo, nf2;
            switch (yy) {
                case -2: olo = -2; nf2 = 2; break;   // even
                case -1: olo = -3; nf2 = 4; break;   // odd
                case  0: olo = -6; nf2 = 6; break;   // even
                case  1: olo = -5; nf2 = 5; break;   // odd
                case  2: olo = -6; nf2 = 6; break;   // even
                case  3: olo = -5; nf2 = 4; break;   // odd
                default: olo = -2; nf2 = 2; break;   // yy=4, even
            }
            (void)lo; (void)lo_raw; (void)hi_raw;
            float yv[12];
#pragma unroll
            for (int k = 0; k < 6; k++) {
                if (k < nf2) {
                    float2 v = reinterpret_cast<const float2*>(
                        hyp + (size_t)(r + yy) * HYS + (j0 + olo))[k];
                    yv[2*k] = v.x; yv[2*k+1] = v.y;
                }
            }
#pragma unroll
            for (int q = 0; q < 2; q++) {
#define X(d) yv[(q) + (d) - olo]
                if (M2) acc[yy+2][q] += -u * X(-2) + u * X(0);
                if (M1) acc[yy+1][q] += c01 * X(-2) + c11 * X(-1) + cKF * X(0)
                                      + KF1 * X(1) + KF2 * X(2) + KF3 * X(3);
                if (Y0) acc[yy][q]   += KB0 * X(-5) + KB1 * X(-4) + KB2 * X(-3)
                                      + cKB * X(-2) - u * X(0);
                if (P1) acc[yy-1][q] += -u * X(-2) + u * X(0);
#undef X
            }
        }

        // ---- Hx rows r-5..r+6 (even stride; origins always even) ----
#pragma unroll
        for (int xx = -5; xx <= 6; xx++) {
            const bool kb0 = (xx + 5 >= 0) && (xx + 5 <= 3);
            const bool kb1 = (xx + 4 >= 0) && (xx + 4 <= 3);
            const bool kb2 = (xx + 3 >= 0) && (xx + 3 <= 3);
            const bool m2  = (xx + 2 >= 0) && (xx + 2 <= 3);
            const bool cc  = (xx + 1 >= 0) && (xx + 1 <= 3);
            const bool mn  = (xx     >= 0) && (xx     <= 3);
            const bool kf1 = (xx - 1 >= 0) && (xx - 1 <= 3);
            const bool kf2 = (xx - 2 >= 0) && (xx - 2 <= 3);
            const bool kf3 = (xx - 3 >= 0) && (xx - 3 <= 3);
            // spans: KB roles d in [0,1]; m2/mn: [-2,2]; cc/kf: [-1,0]
            int olo, nf2;
            if (m2 || mn)            { olo = -2; nf2 = 3; }
            else if (cc || kf1 || kf2 || kf3) { olo = -2; nf2 = 2; }
            else                     { olo =  0; nf2 = 1; }
            float xv[6];
#pragma unroll
            for (int k = 0; k < 3; k++) {
                if (k < nf2) {
                    float2 v = reinterpret_cast<const float2*>(
                        hx + (size_t)(r + xx) * HXS + (j0 + olo))[k];
                    xv[2*k] = v.x; xv[2*k+1] = v.y;
                }
            }
#pragma unroll
            for (int q = 0; q < 2; q++) {
#define X(d) xv[(q) + (d) - olo]
                if (kb0) acc[xx+5][q] -= KB0 * X(0);
                if (kb1) acc[xx+4][q] -= KB1 * X(0);
                if (kb2) acc[xx+3][q] -= KB2 * X(0);
                if (m2)  acc[xx+2][q] -= -u * X(-2) + c01 * X(-1) + cKB * X(0) - u * X(1);
                if (cc)  acc[xx+1][q] -= c11 * X(-1);
                if (mn)  acc[xx][q]   -=  u * X(-2) + cKF * X(-1) - u * X(0) + u * X(1);
                if (kf1) acc[xx-1][q] -= KF1 * X(-1);
                if (kf2) acc[xx-2][q] -= KF2 * X(-1);
                if (kf3) acc[xx-3][q] -= KF3 * X(-1);
#undef X
            }
        }

        // ---- epilogue (E parity batch-dependent -> scalar) ----
#pragma unroll
        for (int o = 0; o < 4; o++) {
            const int i = r + o;
            float ev[2];
            ldrow_s<2>(ev, ein + (size_t)i * ES + j0);
            eo[(size_t)i * ES + j0]     = ev[0] + CFLc * acc[o][0];
            eo[(size_t)i * ES + j0 + 1] = ev[1] + CFLc * acc[o][1];
        }
        return;
    }

    // ---- generic path (edges) ----
#define HXg(rr,cc) hx[(rr) * HXS + (cc)]
#define HYg(rr,cc) hyp[(rr) * HYS + (cc)]
    for (int rr = 0; rr < 4; rr++) {
        const int i = r + rr;
        if (i > NN) break;
#pragma unroll
        for (int q = 0; q < 2; q++) {
            const int j = j0 + q;
            if (j > NN) break;

            const bool iin = (i >= 2) && (i <= NN - 2);
            const bool jin = (j >= 2) && (j <= NN - 2);

            float s1 = 0.0f;
            if (iin && jin) {
                s1 += -u  * HYg(i-2, j-2) + u   * HYg(i-2, j)
                    + c01 * HYg(i-1, j-2) + c11 * HYg(i-1, j-1) + c21 * HYg(i-1, j)
                    + u   * HYg(i  , j-2) - u   * HYg(i  , j)
                    - u   * HYg(i+1, j-2) + u   * HYg(i+1, j);
            }
            if (i >= 1 && j <= NN - 5)
                s1 += KF0*HYg(i-1, j) + KF1*HYg(i-1, j+1) + KF2*HYg(i-1, j+2) + KF3*HYg(i-1, j+3);
            if (i <= NN - 1 && j >= 5)
                s1 += KB0*HYg(i, j-5) + KB1*HYg(i, j-4) + KB2*HYg(i, j-3) + KB3*HYg(i, j-2);
            if (iin && (j == 1 || j == 2))
                s1 += -HYg(i-1, j-1) + 3.0f*HYg(i-1, j) - 3.0f*HYg(i-1, j+1) + HYg(i-1, j+2);
            if (iin && (j == NN-2 || j == NN-1))
                s1 += HYg(i, j-4) - 3.0f*HYg(i, j-3) + 3.0f*HYg(i, j-2) - HYg(i, j-1);

            float s2 = 0.0f;
            if (iin && jin) {
                s2 += -u  * HXg(i-2, j-2) + c01 * HXg(i-2, j-1) + u * HXg(i-2, j) - u * HXg(i-2, j+1)
                    + c11 * HXg(i-1, j-1)
                    + u   * HXg(i  , j-2) + c21 * HXg(i  , j-1) - u * HXg(i  , j) + u * HXg(i  , j+1);
            }
            if (i <= NN - 5 && j >= 1)
                s2 += KF0*HXg(i, j-1) + KF1*HXg(i+1, j-1) + KF2*HXg(i+2, j-1) + KF3*HXg(i+3, j-1);
            if (i >= 5 && j <= NN - 1)
                s2 += KB0*HXg(i-5, j) + KB1*HXg(i-4, j) + KB2*HXg(i-3, j) + KB3*HXg(i-2, j);
            if ((i == 1 || i == 2) && jin)
                s2 += -HXg(i-1, j-1) + 3.0f*HXg(i, j-1) - 3.0f*HXg(i+1, j-1) + HXg(i+2, j-1);
            if ((i == NN-2 || i == NN-1) && jin)
                s2 += HXg(i-4, j) - 3.0f*HXg(i-3, j) + 3.0f*HXg(i-2, j) - HXg(i-1, j);

            eo[(size_t)i * ES + j] = ein[(size_t)i * ES + j] + CFLc * (s1 - s2);
        }
    }
#undef HXg
#undef HYg
}

// ---------------------------------------------------------------------------
// Faraday (R16): 2-row, fast path templated on E parity PB = b&1.
// ---------------------------------------------------------------------------
template<int PB>
__device__ __forceinline__ void faraday_fast(
    const float* __restrict__ ein, const float* __restrict__ hx,
    const float* __restrict__ hyp,
    float* __restrict__ hxo, float* __restrict__ hyo,
    int i0, int j0, float u, float c01, float c11, float c21)
{
    constexpr int OM1 = (PB == 0) ? -1 : 0;   constexpr int NM1 = (PB == 0) ? 3 : 2;
    constexpr int O0  = (PB == 0) ? -2 : -1;  constexpr int N0  = (PB == 0) ? 4 : 3;
    constexpr int O1  = (PB == 0) ? -1 : -2;  constexpr int N1  = (PB == 0) ? 3 : 4;
    constexpr int O2  = (PB == 0) ? -2 : -1;  constexpr int N2  = 3;
    constexpr int O3  = (PB == 0) ? -1 : -2;  constexpr int N3  = 3;
    constexpr int O4  = (PB == 0) ?  0 : -1;  constexpr int N4  = (PB == 0) ? 1 : 2;

    float fm1[2*NM1], f0b[2*N0], f1b[2*N1], f2b[2*N2], f3b[2*N3], f4b[2*N4];
    ldrow_v<NM1>(fm1, ein + (size_t)(i0-1) * ES + (j0 + OM1));
    ldrow_v<N0> (f0b, ein + (size_t)(i0  ) * ES + (j0 + O0));
    ldrow_v<N1> (f1b, ein + (size_t)(i0+1) * ES + (j0 + O1));
    ldrow_v<N2> (f2b, ein + (size_t)(i0+2) * ES + (j0 + O2));
    ldrow_v<N3> (f3b, ein + (size_t)(i0+3) * ES + (j0 + O3));
    ldrow_v<N4> (f4b, ein + (size_t)(i0+4) * ES + (j0 + O4));

#define FM1(d) fm1[q + (d) - OM1]
#define F0(d)  f0b[q + (d) - O0]
#define F1(d)  f1b[q + (d) - O1]
#define F2(d)  f2b[q + (d) - O2]
#define F3(d)  f3b[q + (d) - O3]
#define F4(d)  f4b[q + (d) - O4]

    float s3v[2][2], s4v[2][2];
#pragma unroll
    for (int q = 0; q < 2; q++) {
        s3v[0][q] = 0.5f * FM1(1)
                  - u * F0(-1) + c01 * F0(0) + (u - 2.0f) * F0(1) - u * F0(2)
                  + (c11 - 1.5f) * F1(0) + 1.5f * F1(1)
                  + u * F2(-1) + (c21 + 2.0f) * F2(0) - u * F2(1) + u * F2(2)
                  - 0.5f * F3(0);
        s4v[0][q] = -u * FM1(0) + u * FM1(2)
                  + c01 * F0(0) + (c11 - 1.5f) * F0(1)
                  + (c21 + 2.0f) * F0(2) - 0.5f * F0(3)
                  + 0.5f * F1(-1) + (u - 2.0f) * F1(0) + 1.5f * F1(1) - u * F1(2)
                  - u * F2(0) + u * F2(2);
        s3v[1][q] = 0.5f * F0(1)
                  - u * F1(-1) + c01 * F1(0) + (u - 2.0f) * F1(1) - u * F1(2)
                  + (c11 - 1.5f) * F2(0) + 1.5f * F2(1)
                  + u * F3(-1) + (c21 + 2.0f) * F3(0) - u * F3(1) + u * F3(2)
                  - 0.5f * F4(0);
        s4v[1][q] = -u * F0(0) + u * F0(2)
                  + c01 * F1(0) + (c11 - 1.5f) * F1(1)
                  + (c21 + 2.0f) * F1(2) - 0.5f * F1(3)
                  + 0.5f * F2(-1) + (u - 2.0f) * F2(0) + 1.5f * F2(1) - u * F2(2)
                  - u * F3(0) + u * F3(2);
    }
#undef FM1
#undef F0
#undef F1
#undef F2
#undef F3
#undef F4

    {
        float hyv[2];
        ldrow_v<1>(hyv, hyp + (size_t)i0 * HYS + j0);
        float2 hxp = *reinterpret_cast<const float2*>(hx + (size_t)i0 * HXS + j0);
        const float x0 = hxp.x - CFLc * s3v[0][0];
        const float x1 = hxp.y - CFLc * s3v[0][1];
        const float y0 = hyv[0] + CFLc * s4v[0][0];
        const float y1 = hyv[1] + CFLc * s4v[0][1];
        *reinterpret_cast<float2*>(hxo + (size_t)i0 * HXS + j0) = make_float2(x0, x1);
        *reinterpret_cast<float2*>(hyo + (size_t)i0 * HYS + j0) = make_float2(y0, y1);
    }
    {
        const int i = i0 + 1;
        float hyv[2];
        ldrow_s<2>(hyv, hyp + (size_t)i * HYS + j0);
        float2 hxp = *reinterpret_cast<const float2*>(hx + (size_t)i * HXS + j0);
        const float x0 = hxp.x - CFLc * s3v[1][0];
        const float x1 = hxp.y - CFLc * s3v[1][1];
        *reinterpret_cast<float2*>(hxo + (size_t)i * HXS + j0) = make_float2(x0, x1);
        hyo[(size_t)i * HYS + j0]     = hyv[0] + CFLc * s4v[1][0];
        hyo[(size_t)i * HYS + j0 + 1] = hyv[1] + CFLc * s4v[1][1];
    }
}

__global__ __launch_bounds__(256, 6) void faraday_kernel(
    const float* __restrict__ E, const float* __restrict__ Hx,
    const float* __restrict__ Hy,
    float* __restrict__ Hxo, float* __restrict__ Hyo)
{
    const int jb = blockIdx.x * 128;
    const int R0 = blockIdx.y * 8;
    const int tx = threadIdx.x;
    const int i0 = R0 + threadIdx.y * 2;
    const int j0 = jb + 2 * tx;
    const int b  = blockIdx.z;

    const float* __restrict__ ein = E  + (size_t)b * ESZ;
    const float* __restrict__ hx  = Hx + (size_t)b * HXSZ;
    const float* __restrict__ hyp = Hy + (size_t)b * HYSZ;
    float* __restrict__ hxo = Hxo + (size_t)b * HXSZ;
    float* __restrict__ hyo = Hyo + (size_t)b * HYSZ;

    const float u  = g_coef[0];
    const float dl = g_coef[1];
    const float c01 = u + dl - 0.5f;
    const float c11 = -2.0f * dl;
    const float c21 = dl + 0.5f - u;

    const bool fast = (R0 >= 8) && (R0 + 7 <= NN - 4) &&
                      (jb >= 128) && (jb + 127 <= NN - 4);

    if (fast) {
        if ((b & 1) == 0)
            faraday_fast<0>(ein, hx, hyp, hxo, hyo, i0, j0, u, c01, c11, c21);
        else
            faraday_fast<1>(ein, hx, hyp, hxo, hyo, i0, j0, u, c01, c11, c21);
        return;
    }

    // ---- generic path (edges) ----
#define EEg(rr,cc) ein[(rr) * ES + (cc)]
    for (int rr = 0; rr < 2; rr++) {
        const int i = i0 + rr;
        if (i >= NN) break;
#pragma unroll
        for (int q = 0; q < 2; q++) {
            const int j = j0 + q;
            if (j >= NN) break;

            if (i <= NN - 2) {
                float s3 = 0.0f;
                if (j >= 1 && j <= NN - 2) {
                    s3 += -u  * EEg(i  , j-1) + c01 * EEg(i  , j) + u * EEg(i  , j+1) - u * EEg(i  , j+2)
                        + c11 * EEg(i+1, j)
                        + u   * EEg(i+2, j-1) + c21 * EEg(i+2, j) - u * EEg(i+2, j+1) + u * EEg(i+2, j+2);
                }
                if (i <= NN - 4)
                    s3 += -1.5f * EEg(i+1, j) + 2.0f * EEg(i+2, j) - 0.5f * EEg(i+3, j);
                if (i >= 2)
                    s3 +=  0.5f * EEg(i-1, j+1) - 2.0f * EEg(i, j+1) + 1.5f * EEg(i+1, j+1);
                hxo[(size_t)i * HXS + j] = hx[(size_t)i * HXS + j] - CFLc * s3;
            }

            if (j <= NN - 2) {
                float s4 = 0.0f;
                if (i >= 1 && i <= NN - 2) {
                    s4 += -u  * EEg(i-1, j) + u * EEg(i-1, j+2)
                        + c01 * EEg(i  , j) + c11 * EEg(i, j+1) + c21 * EEg(i, j+2)
                        + u   * EEg(i+1, j) - u * EEg(i+1, j+2)
                        - u   * EEg(i+2, j) + u * EEg(i+2, j+2);
                }
                if (j <= NN - 4)
                    s4 += -1.5f * EEg(i, j+1) + 2.0f * EEg(i, j+2) - 0.5f * EEg(i, j+3);
                if (j >= 2)
                    s4 +=  0.5f * EEg(i+1, j-1) - 2.0f * EEg(i+1, j) + 1.5f * EEg(i+1, j+1);
                hyo[(size_t)i * HYS + j] = hyp[(size_t)i * HYS + j] + CFLc * s4;
            }
        }
    }
#undef EEg
}

// ---------------------------------------------------------------------------
extern "C" void kernel_launch(void* const* d_in, const int* in_sizes, int n_in,
                              void* d_out, int out_size)
{
    const float* E0    = (const float*)d_in[0];
    const float* Hx0   = (const float*)d_in[1];
    const float* Hy0   = (const float*)d_in[2];
    const float* beta  = (const float*)d_in[3];
    const float* delta = (const float*)d_in[4];
    const float* gamma = (const float*)d_in[5];

    float* out = (float*)d_out;
    const size_t esz  = (size_t)BB * ESZ;
    const size_t hxsz = (size_t)BB * HXSZ;
    const size_t hysz = (size_t)BB * HYSZ;

    float* E2  = out;
    float* Hx2 = E2  + esz;
    float* Hy2 = Hx2 + hxsz;
    float* E3  = Hy2 + hysz;
    float* Hx3 = E3  + esz;
    float* Hy3 = Hx3 + hxsz;
    float* E4  = Hy3 + hysz;
    float* Hx4 = E4  + esz;
    float* Hy4 = Hx4 + hxsz;

    coef_kernel<<<1, 1>>>(beta, delta, gamma);

    dim3 blk(64, 4, 1);
    dim3 gE(17, (ES + 15) / 16, BB);   // 17 x 129 x 2 (amper: 16 rows/block)
    dim3 gF(16, NN / 8, BB);           // 16 x 256 x 2 (faraday: 8 rows/block)

    // step 1
    amper_kernel  <<<gE, blk>>>(E0, Hx0, Hy0, E2);
    faraday_kernel<<<gF, blk>>>(E2, Hx0, Hy0, Hx2, Hy2);
    // step 2
    amper_kernel  <<<gE, blk>>>(E2, Hx2, Hy2, E3);
    faraday_kernel<<<gF, blk>>>(E3, Hx2, Hy2, Hx3, Hy3);
    // step 3
    amper_kernel  <<<gE, blk>>>(E3, Hx3, Hy3, E4);
    faraday_kernel<<<gF, blk>>>(E4, Hx3, Hy3, Hx4, Hy4);
}